// round 1
// baseline (speedup 1.0000x reference)
#include <cuda_runtime.h>
#include <math.h>

// Problem constants
#define BB 2
#define TT 2048
#define EE 1024
#define HH 16
#define DD 64
#define MM (BB * TT)          // 4096 rows of hidden
#define BH (BB * HH)          // 32 head-batches

// Scratch (device globals; allocation-free)
__device__ float g_Q[BH * TT * DD];     // [bh, t, d]
__device__ float g_K[BH * TT * DD];
__device__ float g_V[BH * TT * DD];
__device__ float g_attn[MM * EE];       // [b*T+t, h*D+d]

// ---------------------------------------------------------------------------
// Kernel 1: fused QKV projection.
// C[m, n] for n in [0,3072): mat=n/1024 (Q,K,V), h=(n%1024)/64, d=n%64.
// Tiles: BM=64, BN=64 (one head per N tile), BK=16. 256 threads, 4x4 per thread.
// ---------------------------------------------------------------------------
__global__ __launch_bounds__(256) void qkv_gemm(
    const float* __restrict__ X,
    const float* __restrict__ Wq, const float* __restrict__ bq,
    const float* __restrict__ Wk, const float* __restrict__ bk,
    const float* __restrict__ Wv, const float* __restrict__ bv)
{
    __shared__ float As[16][65];   // [k][m], padded
    __shared__ float Bs[16][64];   // [k][n]

    const int bx  = blockIdx.x;          // 0..47
    const int m0  = blockIdx.y * 64;
    const int mat = bx >> 4;              // 0=Q,1=K,2=V
    const int h   = bx & 15;

    const float* W    = (mat == 0 ? Wq : (mat == 1 ? Wk : Wv)) + h * EE * DD;
    const float* bias = (mat == 0 ? bq : (mat == 1 ? bk : bv)) + h * DD;
    float* dst        = (mat == 0 ? g_Q : (mat == 1 ? g_K : g_V));

    const int tid = threadIdx.x;
    const int tx  = tid & 15;
    const int ty  = tid >> 4;

    // A-load: one float4 per thread per k-tile
    const int aRow = tid >> 2;            // 0..63
    const int aK4  = (tid & 3) * 4;       // 0,4,8,12
    // B-load: one float4 per thread per k-tile
    const int bK  = tid >> 4;             // 0..15
    const int bC4 = (tid & 15) * 4;       // 0..60

    float acc[4][4] = {};

    for (int k0 = 0; k0 < EE; k0 += 16) {
        float4 a = *reinterpret_cast<const float4*>(X + (m0 + aRow) * EE + k0 + aK4);
        As[aK4 + 0][aRow] = a.x;
        As[aK4 + 1][aRow] = a.y;
        As[aK4 + 2][aRow] = a.z;
        As[aK4 + 3][aRow] = a.w;
        float4 w = *reinterpret_cast<const float4*>(W + (k0 + bK) * DD + bC4);
        *reinterpret_cast<float4*>(&Bs[bK][bC4]) = w;
        __syncthreads();

#pragma unroll
        for (int k = 0; k < 16; k++) {
            float ra[4], rb[4];
#pragma unroll
            for (int i = 0; i < 4; i++) ra[i] = As[k][ty * 4 + i];
#pragma unroll
            for (int j = 0; j < 4; j++) rb[j] = Bs[k][tx * 4 + j];
#pragma unroll
            for (int i = 0; i < 4; i++)
#pragma unroll
                for (int j = 0; j < 4; j++) acc[i][j] = fmaf(ra[i], rb[j], acc[i][j]);
        }
        __syncthreads();
    }

#pragma unroll
    for (int i = 0; i < 4; i++) {
        const int m  = m0 + ty * 4 + i;
        const int b  = m >> 11;           // /2048
        const int t  = m & (TT - 1);
        float* drow  = dst + ((b * HH + h) * TT + t) * DD;
#pragma unroll
        for (int j = 0; j < 4; j++) {
            const int d = tx * 4 + j;
            drow[d] = acc[i][j] + bias[d];
        }
    }
}

// ---------------------------------------------------------------------------
// Kernel 2: flash attention, fp32. One CTA = one (bh, 64-query-row block).
// Key tiles of 64. Online softmax. 256 threads (16x16), 4x4 per thread.
// Dynamic smem: Qs/Ks/Vs/Ps each 64x65 floats = 66560 B.
// ---------------------------------------------------------------------------
#define ATTN_SMEM (4 * 64 * 65 * (int)sizeof(float))

__global__ __launch_bounds__(256) void flash_attn()
{
    extern __shared__ float sm[];
    float* Qs = sm;                 // [64][65], pre-scaled by 1/sqrt(D)
    float* Ks = Qs + 64 * 65;       // [64][65]
    float* Vs = Ks + 64 * 65;       // [64][65]
    float* Ps = Vs + 64 * 65;       // [64][65]

    const int bh = blockIdx.y;      // 0..31
    const int q0 = blockIdx.x * 64; // query row base

    const float* Qg = g_Q + (bh * TT + q0) * DD;
    const float* Kg = g_K + bh * TT * DD;
    const float* Vg = g_V + bh * TT * DD;

    const int tid = threadIdx.x;
    const int tx  = tid & 15;
    const int ty  = tid >> 4;

    const float scale = 0.125f;     // 1/sqrt(64)

    // Load+scale Q block
#pragma unroll
    for (int i = 0; i < 4; i++) {
        const int idx = tid + i * 256;
        const int r   = idx >> 4;
        const int c4  = (idx & 15) * 4;
        float4 q = *reinterpret_cast<const float4*>(Qg + r * DD + c4);
        Qs[r * 65 + c4 + 0] = q.x * scale;
        Qs[r * 65 + c4 + 1] = q.y * scale;
        Qs[r * 65 + c4 + 2] = q.z * scale;
        Qs[r * 65 + c4 + 3] = q.w * scale;
    }

    float m_i[4], l_i[4], o[4][4];
#pragma unroll
    for (int i = 0; i < 4; i++) {
        m_i[i] = -1e30f;
        l_i[i] = 0.f;
#pragma unroll
        for (int c = 0; c < 4; c++) o[i][c] = 0.f;
    }

    for (int kb = 0; kb < TT / 64; kb++) {
        __syncthreads();   // prev PV reads done (and Q visible on iter 0)

        // Load K, V tiles
#pragma unroll
        for (int i = 0; i < 4; i++) {
            const int idx = tid + i * 256;
            const int r   = idx >> 4;
            const int c4  = (idx & 15) * 4;
            float4 kv = *reinterpret_cast<const float4*>(Kg + (kb * 64 + r) * DD + c4);
            Ks[r * 65 + c4 + 0] = kv.x;
            Ks[r * 65 + c4 + 1] = kv.y;
            Ks[r * 65 + c4 + 2] = kv.z;
            Ks[r * 65 + c4 + 3] = kv.w;
            float4 vv = *reinterpret_cast<const float4*>(Vg + (kb * 64 + r) * DD + c4);
            Vs[r * 65 + c4 + 0] = vv.x;
            Vs[r * 65 + c4 + 1] = vv.y;
            Vs[r * 65 + c4 + 2] = vv.z;
            Vs[r * 65 + c4 + 3] = vv.w;
        }
        __syncthreads();

        // S = Q K^T  (scaled, since Q is pre-scaled)
        float s[4][4] = {};
#pragma unroll 8
        for (int kd = 0; kd < 64; kd++) {
            float q[4], k[4];
#pragma unroll
            for (int i = 0; i < 4; i++) q[i] = Qs[(ty * 4 + i) * 65 + kd];
#pragma unroll
            for (int j = 0; j < 4; j++) k[j] = Ks[(tx * 4 + j) * 65 + kd];
#pragma unroll
            for (int i = 0; i < 4; i++)
#pragma unroll
                for (int j = 0; j < 4; j++) s[i][j] = fmaf(q[i], k[j], s[i][j]);
        }

        // Online softmax per row (rows are shared across the 16 lanes of a ty-group)
#pragma unroll
        for (int i = 0; i < 4; i++) {
            float mx = fmaxf(fmaxf(s[i][0], s[i][1]), fmaxf(s[i][2], s[i][3]));
#pragma unroll
            for (int off = 8; off >= 1; off >>= 1)
                mx = fmaxf(mx, __shfl_xor_sync(0xffffffffu, mx, off, 16));
            const float mnew  = fmaxf(m_i[i], mx);
            const float alpha = __expf(m_i[i] - mnew);
            float sum = 0.f;
#pragma unroll
            for (int j = 0; j < 4; j++) {
                const float p = __expf(s[i][j] - mnew);
                s[i][j] = p;
                sum += p;
            }
#pragma unroll
            for (int off = 8; off >= 1; off >>= 1)
                sum += __shfl_xor_sync(0xffffffffu, sum, off, 16);
            l_i[i] = l_i[i] * alpha + sum;
            m_i[i] = mnew;
#pragma unroll
            for (int c = 0; c < 4; c++) o[i][c] *= alpha;
        }

        // Share P
#pragma unroll
        for (int i = 0; i < 4; i++)
#pragma unroll
            for (int j = 0; j < 4; j++)
                Ps[(ty * 4 + i) * 65 + tx * 4 + j] = s[i][j];
        __syncthreads();

        // O += P V
#pragma unroll 4
        for (int j = 0; j < 64; j++) {
            float pr[4], v[4];
#pragma unroll
            for (int i = 0; i < 4; i++) pr[i] = Ps[(ty * 4 + i) * 65 + j];
#pragma unroll
            for (int c = 0; c < 4; c++) v[c] = Vs[j * 65 + tx * 4 + c];
#pragma unroll
            for (int i = 0; i < 4; i++)
#pragma unroll
                for (int c = 0; c < 4; c++) o[i][c] = fmaf(pr[i], v[c], o[i][c]);
        }
    }

    // Epilogue: normalize, write to g_attn [b*T+t, h*64+d]
    const int b = bh >> 4;
    const int h = bh & 15;
#pragma unroll
    for (int i = 0; i < 4; i++) {
        const int t = q0 + ty * 4 + i;
        const float inv = 1.f / l_i[i];
        float* row = g_attn + (b * TT + t) * EE + h * DD;
#pragma unroll
        for (int c = 0; c < 4; c++) row[tx * 4 + c] = o[i][c] * inv;
    }
}

// ---------------------------------------------------------------------------
// Kernel 3: output projection. out[m,e] = sum_k attn[m,k]*gate[k/64]*Wo[k,e]
//                                        + sum_h gate[h]*bo[h,e]
// Wo viewed as [H*D, E] row-major (h*D*E + d*E + e == (h*64+d)*E + e).
// ---------------------------------------------------------------------------
__global__ __launch_bounds__(256) void out_gemm(
    const float* __restrict__ Wo, const float* __restrict__ bo,
    const float* __restrict__ gate, float* __restrict__ out)
{
    __shared__ float As[16][65];
    __shared__ float Bs[16][64];
    __shared__ float gs[HH];

    const int n0 = blockIdx.x * 64;
    const int m0 = blockIdx.y * 64;

    const int tid = threadIdx.x;
    const int tx  = tid & 15;
    const int ty  = tid >> 4;

    if (tid < HH) gs[tid] = gate[tid];
    __syncthreads();

    const int aRow = tid >> 2;
    const int aK4  = (tid & 3) * 4;
    const int bK   = tid >> 4;
    const int bC4  = (tid & 15) * 4;

    float acc[4][4] = {};

    for (int k0 = 0; k0 < EE; k0 += 16) {
        float4 a = *reinterpret_cast<const float4*>(g_attn + (m0 + aRow) * EE + k0 + aK4);
        As[aK4 + 0][aRow] = a.x;
        As[aK4 + 1][aRow] = a.y;
        As[aK4 + 2][aRow] = a.z;
        As[aK4 + 3][aRow] = a.w;
        const float g = gs[(k0 + bK) >> 6];
        float4 w = *reinterpret_cast<const float4*>(Wo + (k0 + bK) * EE + n0 + bC4);
        w.x *= g; w.y *= g; w.z *= g; w.w *= g;
        *reinterpret_cast<float4*>(&Bs[bK][bC4]) = w;
        __syncthreads();

#pragma unroll
        for (int k = 0; k < 16; k++) {
            float ra[4], rb[4];
#pragma unroll
            for (int i = 0; i < 4; i++) ra[i] = As[k][ty * 4 + i];
#pragma unroll
            for (int j = 0; j < 4; j++) rb[j] = Bs[k][tx * 4 + j];
#pragma unroll
            for (int i = 0; i < 4; i++)
#pragma unroll
                for (int j = 0; j < 4; j++) acc[i][j] = fmaf(ra[i], rb[j], acc[i][j]);
        }
        __syncthreads();
    }

    // Gated bias per column
    float biasv[4];
#pragma unroll
    for (int j = 0; j < 4; j++) {
        const int e = n0 + tx * 4 + j;
        float s = 0.f;
#pragma unroll
        for (int h = 0; h < HH; h++) s = fmaf(gs[h], bo[h * EE + e], s);
        biasv[j] = s;
    }

#pragma unroll
    for (int i = 0; i < 4; i++) {
        const int m = m0 + ty * 4 + i;
#pragma unroll
        for (int j = 0; j < 4; j++)
            out[m * EE + n0 + tx * 4 + j] = acc[i][j] + biasv[j];
    }
}

// ---------------------------------------------------------------------------
extern "C" void kernel_launch(void* const* d_in, const int* in_sizes, int n_in,
                              void* d_out, int out_size)
{
    const float* X    = (const float*)d_in[0];
    const float* Wq   = (const float*)d_in[1];
    const float* bq   = (const float*)d_in[2];
    const float* Wk   = (const float*)d_in[3];
    const float* bk   = (const float*)d_in[4];
    const float* Wv   = (const float*)d_in[5];
    const float* bv   = (const float*)d_in[6];
    const float* Wo   = (const float*)d_in[7];
    const float* bo   = (const float*)d_in[8];
    const float* gate = (const float*)d_in[9];
    float* out = (float*)d_out;

    cudaFuncSetAttribute(flash_attn, cudaFuncAttributeMaxDynamicSharedMemorySize, ATTN_SMEM);

    // 1) QKV projection: grid (48 = 3 mats * 16 heads, 64 M-tiles)
    qkv_gemm<<<dim3(48, 64), 256>>>(X, Wq, bq, Wk, bk, Wv, bv);
    // 2) Flash attention: grid (32 query blocks, 32 head-batches)
    flash_attn<<<dim3(TT / 64, BH), 256, ATTN_SMEM>>>();
    // 3) Output projection: grid (16 N-tiles, 64 M-tiles)
    out_gemm<<<dim3(EE / 64, MM / 64), 256>>>(Wo, bo, gate, out);
}

// round 3
// speedup vs baseline: 1.5643x; 1.5643x over previous
#include <cuda_runtime.h>
#include <mma.h>
#include <cstdint>
#include <math.h>

using namespace nvcuda;

// ---------------------------------------------------------------------------
// Problem constants
// ---------------------------------------------------------------------------
#define BB 2
#define TT 2048
#define EE 1024
#define HH 16
#define DD 64
#define MM (BB * TT)          // 4096 rows
#define BH (BB * HH)          // 32 head-batches

// Scratch (device globals; allocation-free)
__device__ float g_Q[BH * TT * DD];
__device__ float g_K[BH * TT * DD];
__device__ float g_V[BH * TT * DD];
__device__ float g_attn[MM * EE];

// Round fp32 -> tf32 bit pattern (round-to-nearest-even on 10-bit mantissa)
__device__ __forceinline__ float f2tf32f(float x) {
    uint32_t u;
    asm("cvt.rna.tf32.f32 %0, %1;" : "=r"(u) : "f"(x));
    return __uint_as_float(u);
}
__device__ __forceinline__ float4 f2tf32v(float4 v) {
    return make_float4(f2tf32f(v.x), f2tf32f(v.y), f2tf32f(v.z), f2tf32f(v.w));
}

typedef wmma::fragment<wmma::matrix_a, 16, 16, 8, wmma::precision::tf32, wmma::row_major> FragA;
typedef wmma::fragment<wmma::matrix_b, 16, 16, 8, wmma::precision::tf32, wmma::row_major> FragB;
typedef wmma::fragment<wmma::matrix_b, 16, 16, 8, wmma::precision::tf32, wmma::col_major> FragBT;
typedef wmma::fragment<wmma::accumulator, 16, 16, 8, float> FragC;

// ---------------------------------------------------------------------------
// GEMM smem layout (static, unioned):
//   phase 1: As[128][40] (20480 B) | Bs[32][72] (9216 B)
//   phase 2: Cs[128][68] (34816 B)
// ---------------------------------------------------------------------------
#define A_LD 40
#define B_LD 72
#define C_LD 68
#define GEMM_SMEM_BYTES 34816

// ---------------------------------------------------------------------------
// Kernel 1: fused QKV projection, wmma tf32.
// grid.x = 48 (mat*16 + head, N-tile = 64 = one head), grid.y = 32 (M/128)
// ---------------------------------------------------------------------------
__global__ __launch_bounds__(256) void qkv_gemm_tc(
    const float* __restrict__ X,
    const float* __restrict__ Wq, const float* __restrict__ bq,
    const float* __restrict__ Wk, const float* __restrict__ bk,
    const float* __restrict__ Wv, const float* __restrict__ bv)
{
    __shared__ __align__(16) char smbuf[GEMM_SMEM_BYTES];
    float* As = reinterpret_cast<float*>(smbuf);
    float* Bs = reinterpret_cast<float*>(smbuf + 20480);
    float* Cs = reinterpret_cast<float*>(smbuf);

    const int bx  = blockIdx.x;
    const int m0  = blockIdx.y * 128;
    const int mat = bx >> 4;
    const int h   = bx & 15;

    const float* W    = (mat == 0 ? Wq : (mat == 1 ? Wk : Wv)) + (size_t)h * EE * DD;
    const float* bias = (mat == 0 ? bq : (mat == 1 ? bk : bv)) + h * DD;
    float* dst        = (mat == 0 ? g_Q : (mat == 1 ? g_K : g_V));

    const int tid = threadIdx.x;
    const int wid = tid >> 5;
    const int wrow = (wid >> 1) * 32;   // 0,32,64,96
    const int wcol = (wid & 1) * 32;    // 0,32

    FragC c[2][2];
#pragma unroll
    for (int i = 0; i < 2; i++)
#pragma unroll
        for (int j = 0; j < 2; j++) wmma::fill_fragment(c[i][j], 0.0f);

    for (int kt = 0; kt < 32; kt++) {
        const int k0 = kt * 32;
        __syncthreads();
        // Load A: 128x32 (1024 float4), 4 per thread
#pragma unroll
        for (int i = 0; i < 4; i++) {
            const int f = tid + i * 256;
            const int r = f >> 3;
            const int cc = f & 7;
            float4 v = *reinterpret_cast<const float4*>(X + (size_t)(m0 + r) * EE + k0 + cc * 4);
            *reinterpret_cast<float4*>(As + r * A_LD + cc * 4) = f2tf32v(v);
        }
        // Load B: 32x64 (512 float4), 2 per thread
#pragma unroll
        for (int i = 0; i < 2; i++) {
            const int f = tid + i * 256;
            const int r = f >> 4;
            const int cc = f & 15;
            float4 v = *reinterpret_cast<const float4*>(W + (size_t)(k0 + r) * DD + cc * 4);
            *reinterpret_cast<float4*>(Bs + r * B_LD + cc * 4) = f2tf32v(v);
        }
        __syncthreads();

#pragma unroll
        for (int ks = 0; ks < 4; ks++) {
            FragA a[2];
            FragB b[2];
#pragma unroll
            for (int i = 0; i < 2; i++)
                wmma::load_matrix_sync(a[i], As + (wrow + i * 16) * A_LD + ks * 8, A_LD);
#pragma unroll
            for (int j = 0; j < 2; j++)
                wmma::load_matrix_sync(b[j], Bs + (ks * 8) * B_LD + wcol + j * 16, B_LD);
#pragma unroll
            for (int i = 0; i < 2; i++)
#pragma unroll
                for (int j = 0; j < 2; j++)
                    wmma::mma_sync(c[i][j], a[i], b[j], c[i][j]);
        }
    }

    __syncthreads();
#pragma unroll
    for (int i = 0; i < 2; i++)
#pragma unroll
        for (int j = 0; j < 2; j++)
            wmma::store_matrix_sync(Cs + (wrow + i * 16) * C_LD + wcol + j * 16,
                                    c[i][j], C_LD, wmma::mem_row_major);
    __syncthreads();

    // Write out with bias: rows -> [bh, t, d]
#pragma unroll
    for (int i = 0; i < 8; i++) {
        const int f = tid + i * 256;          // 0..2047 float4
        const int r = f >> 4;
        const int c4 = (f & 15) * 4;
        const int m  = m0 + r;
        const int bb = m >> 11;
        const int t  = m & (TT - 1);
        float4 v = *reinterpret_cast<const float4*>(Cs + r * C_LD + c4);
        v.x += bias[c4 + 0];
        v.y += bias[c4 + 1];
        v.z += bias[c4 + 2];
        v.w += bias[c4 + 3];
        *reinterpret_cast<float4*>(dst + ((size_t)((bb * HH + h) * TT + t)) * DD + c4) = v;
    }
}

// ---------------------------------------------------------------------------
// Kernel 3: output projection, wmma tf32, gate folded into B, gated bias.
// grid.x = 16 (N/64), grid.y = 32 (M/128)
// ---------------------------------------------------------------------------
__global__ __launch_bounds__(256) void out_gemm_tc(
    const float* __restrict__ Wo, const float* __restrict__ bo,
    const float* __restrict__ gate, float* __restrict__ out)
{
    __shared__ __align__(16) char smbuf[GEMM_SMEM_BYTES];
    __shared__ float gbias[64];
    __shared__ float gsh[HH];
    float* As = reinterpret_cast<float*>(smbuf);
    float* Bs = reinterpret_cast<float*>(smbuf + 20480);
    float* Cs = reinterpret_cast<float*>(smbuf);

    const int n0 = blockIdx.x * 64;
    const int m0 = blockIdx.y * 128;

    const int tid = threadIdx.x;
    const int wid = tid >> 5;
    const int wrow = (wid >> 1) * 32;
    const int wcol = (wid & 1) * 32;

    if (tid < HH) gsh[tid] = gate[tid];
    __syncthreads();
    if (tid < 64) {
        float s = 0.f;
#pragma unroll
        for (int hh = 0; hh < HH; hh++)
            s = fmaf(gsh[hh], bo[(size_t)hh * EE + n0 + tid], s);
        gbias[tid] = s;
    }

    FragC c[2][2];
#pragma unroll
    for (int i = 0; i < 2; i++)
#pragma unroll
        for (int j = 0; j < 2; j++) wmma::fill_fragment(c[i][j], 0.0f);

    for (int kt = 0; kt < 32; kt++) {
        const int k0 = kt * 32;
        __syncthreads();
#pragma unroll
        for (int i = 0; i < 4; i++) {
            const int f = tid + i * 256;
            const int r = f >> 3;
            const int cc = f & 7;
            float4 v = *reinterpret_cast<const float4*>(g_attn + (size_t)(m0 + r) * EE + k0 + cc * 4);
            *reinterpret_cast<float4*>(As + r * A_LD + cc * 4) = f2tf32v(v);
        }
#pragma unroll
        for (int i = 0; i < 2; i++) {
            const int f = tid + i * 256;
            const int r = f >> 4;
            const int cc = f & 15;
            const float g = gsh[(k0 + r) >> 6];
            float4 v = *reinterpret_cast<const float4*>(Wo + (size_t)(k0 + r) * EE + n0 + cc * 4);
            v.x *= g; v.y *= g; v.z *= g; v.w *= g;
            *reinterpret_cast<float4*>(Bs + r * B_LD + cc * 4) = f2tf32v(v);
        }
        __syncthreads();

#pragma unroll
        for (int ks = 0; ks < 4; ks++) {
            FragA a[2];
            FragB b[2];
#pragma unroll
            for (int i = 0; i < 2; i++)
                wmma::load_matrix_sync(a[i], As + (wrow + i * 16) * A_LD + ks * 8, A_LD);
#pragma unroll
            for (int j = 0; j < 2; j++)
                wmma::load_matrix_sync(b[j], Bs + (ks * 8) * B_LD + wcol + j * 16, B_LD);
#pragma unroll
            for (int i = 0; i < 2; i++)
#pragma unroll
                for (int j = 0; j < 2; j++)
                    wmma::mma_sync(c[i][j], a[i], b[j], c[i][j]);
        }
    }

    __syncthreads();
#pragma unroll
    for (int i = 0; i < 2; i++)
#pragma unroll
        for (int j = 0; j < 2; j++)
            wmma::store_matrix_sync(Cs + (wrow + i * 16) * C_LD + wcol + j * 16,
                                    c[i][j], C_LD, wmma::mem_row_major);
    __syncthreads();

#pragma unroll
    for (int i = 0; i < 8; i++) {
        const int f = tid + i * 256;
        const int r = f >> 4;
        const int c4 = (f & 15) * 4;
        float4 v = *reinterpret_cast<const float4*>(Cs + r * C_LD + c4);
        v.x += gbias[c4 + 0];
        v.y += gbias[c4 + 1];
        v.z += gbias[c4 + 2];
        v.w += gbias[c4 + 3];
        *reinterpret_cast<float4*>(out + (size_t)(m0 + r) * EE + n0 + c4) = v;
    }
}

// ---------------------------------------------------------------------------
// Kernel 2: flash attention, wmma tf32 for QK^T and PV; softmax in fp32.
// One CTA = (bh, 64-query block). 256 threads, 8 warps (4 row-groups x 2).
// Dynamic smem: Qs, Ks, Vs, Ss, PVs each [64][68] fp32 -> 87040 B.
// ---------------------------------------------------------------------------
#define T_LD 68
#define ATTN_SMEM (5 * 64 * T_LD * (int)sizeof(float))

__global__ __launch_bounds__(256) void flash_attn_tc()
{
    extern __shared__ float sm[];
    float* Qs  = sm;                    // [64][68], pre-scaled, tf32
    float* Ks  = Qs  + 64 * T_LD;       // [64][68], tf32
    float* Vs  = Ks  + 64 * T_LD;       // [64][68], tf32
    float* Ss  = Vs  + 64 * T_LD;       // [64][68], scores then P~ (tf32)
    float* PVs = Ss  + 64 * T_LD;       // [64][68], PV partial

    const int bh = blockIdx.y;
    const int q0 = blockIdx.x * 64;

    const float* Qg = g_Q + ((size_t)bh * TT + q0) * DD;
    const float* Kg = g_K + (size_t)bh * TT * DD;
    const float* Vg = g_V + (size_t)bh * TT * DD;

    const int tid = threadIdx.x;
    const int wid = tid >> 5;
    const int wrow = (wid >> 1) * 16;   // 0,16,32,48
    const int wcol = (wid & 1) * 32;    // 0,32

    // Softmax ownership: thread owns row r = tid>>2, col block q = tid&3 (16 cols)
    const int srow = tid >> 2;
    const int scol = (tid & 3) * 16;

    const float scale = 0.125f;

    // Load Q (scaled, tf32)
#pragma unroll
    for (int i = 0; i < 4; i++) {
        const int f = tid + i * 256;       // 0..1023
        const int r = f >> 4;
        const int c4 = (f & 15) * 4;
        float4 v = *reinterpret_cast<const float4*>(Qg + r * DD + c4);
        v.x *= scale; v.y *= scale; v.z *= scale; v.w *= scale;
        *reinterpret_cast<float4*>(Qs + r * T_LD + c4) = f2tf32v(v);
    }

    float m_i = -1e30f, l_i = 0.f;
    float o[16];
#pragma unroll
    for (int j = 0; j < 16; j++) o[j] = 0.f;

    for (int kb = 0; kb < TT / 64; kb++) {
        __syncthreads();   // Ks/Vs/Ss reusable; Qs visible on iter 0
        // Load K, V tiles (tf32)
#pragma unroll
        for (int i = 0; i < 4; i++) {
            const int f = tid + i * 256;
            const int r = f >> 4;
            const int c4 = (f & 15) * 4;
            float4 kv = *reinterpret_cast<const float4*>(Kg + (size_t)(kb * 64 + r) * DD + c4);
            *reinterpret_cast<float4*>(Ks + r * T_LD + c4) = f2tf32v(kv);
            float4 vv = *reinterpret_cast<const float4*>(Vg + (size_t)(kb * 64 + r) * DD + c4);
            *reinterpret_cast<float4*>(Vs + r * T_LD + c4) = f2tf32v(vv);
        }
        __syncthreads();

        // S = Q K^T : warp computes 16x32. A row-major from Qs, B col-major from Ks.
        {
            FragC s[2];
            wmma::fill_fragment(s[0], 0.0f);
            wmma::fill_fragment(s[1], 0.0f);
#pragma unroll
            for (int ks = 0; ks < 8; ks++) {
                FragA a;
                wmma::load_matrix_sync(a, Qs + wrow * T_LD + ks * 8, T_LD);
#pragma unroll
                for (int j = 0; j < 2; j++) {
                    FragBT b;
                    wmma::load_matrix_sync(b, Ks + (wcol + j * 16) * T_LD + ks * 8, T_LD);
                    wmma::mma_sync(s[j], a, b, s[j]);
                }
            }
            wmma::store_matrix_sync(Ss + wrow * T_LD + wcol,      s[0], T_LD, wmma::mem_row_major);
            wmma::store_matrix_sync(Ss + wrow * T_LD + wcol + 16, s[1], T_LD, wmma::mem_row_major);
        }
        __syncthreads();

        // Online softmax; each thread owns 16 columns of one row.
        {
            float p[16];
            float mx = -1e30f;
#pragma unroll
            for (int j = 0; j < 16; j++) {
                p[j] = Ss[srow * T_LD + scol + j];
                mx = fmaxf(mx, p[j]);
            }
            mx = fmaxf(mx, __shfl_xor_sync(0xffffffffu, mx, 1));
            mx = fmaxf(mx, __shfl_xor_sync(0xffffffffu, mx, 2));
            const float mnew  = fmaxf(m_i, mx);
            const float alpha = __expf(m_i - mnew);
            float sum = 0.f;
#pragma unroll
            for (int j = 0; j < 16; j++) {
                p[j] = __expf(p[j] - mnew);
                sum += p[j];
            }
            sum += __shfl_xor_sync(0xffffffffu, sum, 1);
            sum += __shfl_xor_sync(0xffffffffu, sum, 2);
            l_i = l_i * alpha + sum;
            m_i = mnew;
#pragma unroll
            for (int j = 0; j < 16; j++) o[j] *= alpha;
            // write P~ back (tf32)
#pragma unroll
            for (int j = 0; j < 16; j++)
                Ss[srow * T_LD + scol + j] = f2tf32f(p[j]);
        }
        __syncthreads();

        // PV: A = Ss (row-major), B = Vs (row-major), warp 16x32.
        {
            FragC pv[2];
            wmma::fill_fragment(pv[0], 0.0f);
            wmma::fill_fragment(pv[1], 0.0f);
#pragma unroll
            for (int ks = 0; ks < 8; ks++) {
                FragA a;
                wmma::load_matrix_sync(a, Ss + wrow * T_LD + ks * 8, T_LD);
#pragma unroll
                for (int j = 0; j < 2; j++) {
                    FragB b;
                    wmma::load_matrix_sync(b, Vs + (ks * 8) * T_LD + wcol + j * 16, T_LD);
                    wmma::mma_sync(pv[j], a, b, pv[j]);
                }
            }
            wmma::store_matrix_sync(PVs + wrow * T_LD + wcol,      pv[0], T_LD, wmma::mem_row_major);
            wmma::store_matrix_sync(PVs + wrow * T_LD + wcol + 16, pv[1], T_LD, wmma::mem_row_major);
        }
        __syncthreads();

        // Accumulate into O registers (known layout)
#pragma unroll
        for (int j = 0; j < 16; j++)
            o[j] += PVs[srow * T_LD + scol + j];
    }

    // Epilogue: normalize and write to g_attn [b*T+t, h*64+d]
    const int b = bh >> 4;
    const int h = bh & 15;
    const float inv = 1.f / l_i;
    float* row = g_attn + ((size_t)(b * TT + q0 + srow)) * EE + h * DD + scol;
#pragma unroll
    for (int j = 0; j < 16; j += 4) {
        float4 v = make_float4(o[j] * inv, o[j + 1] * inv, o[j + 2] * inv, o[j + 3] * inv);
        *reinterpret_cast<float4*>(row + j) = v;
    }
}

// ---------------------------------------------------------------------------
extern "C" void kernel_launch(void* const* d_in, const int* in_sizes, int n_in,
                              void* d_out, int out_size)
{
    const float* X    = (const float*)d_in[0];
    const float* Wq   = (const float*)d_in[1];
    const float* bq   = (const float*)d_in[2];
    const float* Wk   = (const float*)d_in[3];
    const float* bk   = (const float*)d_in[4];
    const float* Wv   = (const float*)d_in[5];
    const float* bv   = (const float*)d_in[6];
    const float* Wo   = (const float*)d_in[7];
    const float* bo   = (const float*)d_in[8];
    const float* gate = (const float*)d_in[9];
    float* out = (float*)d_out;

    cudaFuncSetAttribute(flash_attn_tc, cudaFuncAttributeMaxDynamicSharedMemorySize, ATTN_SMEM);

    // 1) QKV projection
    qkv_gemm_tc<<<dim3(48, MM / 128), 256>>>(X, Wq, bq, Wk, bk, Wv, bv);
    // 2) Flash attention
    flash_attn_tc<<<dim3(TT / 64, BH), 256, ATTN_SMEM>>>();
    // 3) Output projection
    out_gemm_tc<<<dim3(EE / 64, MM / 128), 256>>>(Wo, bo, gate, out);
}

// round 4
// speedup vs baseline: 2.5049x; 1.6012x over previous
#include <cuda_runtime.h>
#include <mma.h>
#include <cstdint>
#include <math.h>

using namespace nvcuda;

// ---------------------------------------------------------------------------
// Problem constants
// ---------------------------------------------------------------------------
#define BB 2
#define TT 2048
#define EE 1024
#define HH 16
#define DD 64
#define MM (BB * TT)
#define BH (BB * HH)

// Scratch (device globals; allocation-free)
__device__ float g_Q[BH * TT * DD];
__device__ float g_K[BH * TT * DD];
__device__ float g_V[BH * TT * DD];
__device__ float g_attn[MM * EE];   // gated attention output, [b*T+t, h*64+d]

// ---------------------------------------------------------------------------
// Helpers
// ---------------------------------------------------------------------------
__device__ __forceinline__ uint32_t smem_u32(const void* p) {
    return (uint32_t)__cvta_generic_to_shared(p);
}
__device__ __forceinline__ void cp16(uint32_t dst, const void* src) {
    asm volatile("cp.async.cg.shared.global [%0], [%1], 16;\n" :: "r"(dst), "l"(src));
}
__device__ __forceinline__ void cp_commit() {
    asm volatile("cp.async.commit_group;\n" ::: "memory");
}
__device__ __forceinline__ void cp_wait1() {
    asm volatile("cp.async.wait_group 1;\n" ::: "memory");
}
__device__ __forceinline__ void cp_wait0() {
    asm volatile("cp.async.wait_group 0;\n" ::: "memory");
}

// m16n8k8 tf32 mma (HW truncates fp32 operands to tf32)
__device__ __forceinline__ void mma_tf32(float* d, const uint32_t* a,
                                         const uint32_t* b, const float* c) {
    asm volatile(
        "mma.sync.aligned.m16n8k8.row.col.f32.tf32.tf32.f32 "
        "{%0,%1,%2,%3}, {%4,%5,%6,%7}, {%8,%9}, {%10,%11,%12,%13};\n"
        : "=f"(d[0]), "=f"(d[1]), "=f"(d[2]), "=f"(d[3])
        : "r"(a[0]), "r"(a[1]), "r"(a[2]), "r"(a[3]),
          "r"(b[0]), "r"(b[1]),
          "f"(c[0]), "f"(c[1]), "f"(c[2]), "f"(c[3]));
}

typedef wmma::fragment<wmma::matrix_a, 16, 16, 8, wmma::precision::tf32, wmma::row_major> FragA;
typedef wmma::fragment<wmma::matrix_b, 16, 16, 8, wmma::precision::tf32, wmma::row_major> FragB;
typedef wmma::fragment<wmma::accumulator, 16, 16, 8, float> FragC;

// ---------------------------------------------------------------------------
// GEMM smem: 3 stages of (A 128x40 fp32 = 20480 B, B 32x72 fp32 = 9216 B)
// C epilogue (128x68 = 34816 B) overlays stage 0/1.
// ---------------------------------------------------------------------------
#define A_LD 40
#define B_LD 72
#define C_LD 68
#define STAGE_BYTES 29696
#define GEMM_SMEM (3 * STAGE_BYTES)

// ---------------------------------------------------------------------------
// Kernel 1: fused QKV projection (wmma tf32, 3-stage cp.async).
// grid.x = 48 (mat*16 + head), grid.y = 32 (M/128). 256 threads.
// ---------------------------------------------------------------------------
__global__ __launch_bounds__(256) void qkv_gemm_tc(
    const float* __restrict__ X,
    const float* __restrict__ Wq, const float* __restrict__ bq,
    const float* __restrict__ Wk, const float* __restrict__ bk,
    const float* __restrict__ Wv, const float* __restrict__ bv)
{
    extern __shared__ char smc[];
    const uint32_t smb = smem_u32(smc);

    const int bx  = blockIdx.x;
    const int m0  = blockIdx.y * 128;
    const int mat = bx >> 4;
    const int h   = bx & 15;

    const float* W    = (mat == 0 ? Wq : (mat == 1 ? Wk : Wv)) + (size_t)h * EE * DD;
    const float* bias = (mat == 0 ? bq : (mat == 1 ? bk : bv)) + h * DD;
    float* dst        = (mat == 0 ? g_Q : (mat == 1 ? g_K : g_V));

    const int tid = threadIdx.x;
    const int wid = tid >> 5;
    const int wrow = (wid >> 1) * 32;
    const int wcol = (wid & 1) * 32;

    // stage issue
    auto issue = [&](int kt) {
        const int k0 = kt * 32;
        const uint32_t Au = smb + (kt % 3) * STAGE_BYTES;
        const uint32_t Bu = Au + 20480;
#pragma unroll
        for (int i = 0; i < 4; i++) {
            const int ch = tid + i * 256;
            const int r = ch >> 3, c = ch & 7;
            cp16(Au + r * (A_LD * 4) + c * 16, X + (size_t)(m0 + r) * EE + k0 + c * 4);
        }
#pragma unroll
        for (int i = 0; i < 2; i++) {
            const int ch = tid + i * 256;
            const int r = ch >> 4, c = ch & 15;
            cp16(Bu + r * (B_LD * 4) + c * 16, W + (size_t)(k0 + r) * DD + c * 4);
        }
        cp_commit();
    };

    FragC c[2][2];
#pragma unroll
    for (int i = 0; i < 2; i++)
#pragma unroll
        for (int j = 0; j < 2; j++) wmma::fill_fragment(c[i][j], 0.0f);

    issue(0);
    issue(1);

    for (int kt = 0; kt < 32; kt++) {
        if (kt == 31) cp_wait0(); else cp_wait1();
        __syncthreads();
        if (kt + 2 < 32) issue(kt + 2);

        const float* As = reinterpret_cast<const float*>(smc + (kt % 3) * STAGE_BYTES);
        const float* Bs = reinterpret_cast<const float*>(smc + (kt % 3) * STAGE_BYTES + 20480);
#pragma unroll
        for (int ks = 0; ks < 4; ks++) {
            FragA a[2];
            FragB b[2];
#pragma unroll
            for (int i = 0; i < 2; i++)
                wmma::load_matrix_sync(a[i], As + (wrow + i * 16) * A_LD + ks * 8, A_LD);
#pragma unroll
            for (int j = 0; j < 2; j++)
                wmma::load_matrix_sync(b[j], Bs + (ks * 8) * B_LD + wcol + j * 16, B_LD);
#pragma unroll
            for (int i = 0; i < 2; i++)
#pragma unroll
                for (int j = 0; j < 2; j++)
                    wmma::mma_sync(c[i][j], a[i], b[j], c[i][j]);
        }
    }

    __syncthreads();
    float* Cs = reinterpret_cast<float*>(smc);
#pragma unroll
    for (int i = 0; i < 2; i++)
#pragma unroll
        for (int j = 0; j < 2; j++)
            wmma::store_matrix_sync(Cs + (wrow + i * 16) * C_LD + wcol + j * 16,
                                    c[i][j], C_LD, wmma::mem_row_major);
    __syncthreads();

#pragma unroll
    for (int i = 0; i < 8; i++) {
        const int f = tid + i * 256;
        const int r = f >> 4;
        const int c4 = (f & 15) * 4;
        const int m  = m0 + r;
        const int bb = m >> 11;
        const int t  = m & (TT - 1);
        float4 v = *reinterpret_cast<const float4*>(Cs + r * C_LD + c4);
        v.x += bias[c4 + 0];
        v.y += bias[c4 + 1];
        v.z += bias[c4 + 2];
        v.w += bias[c4 + 3];
        *reinterpret_cast<float4*>(dst + ((size_t)((bb * HH + h) * TT + t)) * DD + c4) = v;
    }
}

// ---------------------------------------------------------------------------
// Kernel 3: output projection (wmma tf32, 3-stage cp.async).
// A = g_attn (already gated), B = Wo raw; gated bias in epilogue.
// grid.x = 16 (N/64), grid.y = 32 (M/128). 256 threads.
// ---------------------------------------------------------------------------
__global__ __launch_bounds__(256) void out_gemm_tc(
    const float* __restrict__ Wo, const float* __restrict__ bo,
    const float* __restrict__ gate, float* __restrict__ out)
{
    extern __shared__ char smc[];
    const uint32_t smb = smem_u32(smc);
    __shared__ float gbias[64];

    const int n0 = blockIdx.x * 64;
    const int m0 = blockIdx.y * 128;

    const int tid = threadIdx.x;
    const int wid = tid >> 5;
    const int wrow = (wid >> 1) * 32;
    const int wcol = (wid & 1) * 32;

    if (tid < 64) {
        float s = 0.f;
#pragma unroll
        for (int hh = 0; hh < HH; hh++)
            s = fmaf(gate[hh], bo[(size_t)hh * EE + n0 + tid], s);
        gbias[tid] = s;
    }

    auto issue = [&](int kt) {
        const int k0 = kt * 32;
        const uint32_t Au = smb + (kt % 3) * STAGE_BYTES;
        const uint32_t Bu = Au + 20480;
#pragma unroll
        for (int i = 0; i < 4; i++) {
            const int ch = tid + i * 256;
            const int r = ch >> 3, c = ch & 7;
            cp16(Au + r * (A_LD * 4) + c * 16, g_attn + (size_t)(m0 + r) * EE + k0 + c * 4);
        }
#pragma unroll
        for (int i = 0; i < 2; i++) {
            const int ch = tid + i * 256;
            const int r = ch >> 4, c = ch & 15;
            cp16(Bu + r * (B_LD * 4) + c * 16, Wo + (size_t)(k0 + r) * EE + n0 + c * 4);
        }
        cp_commit();
    };

    FragC c[2][2];
#pragma unroll
    for (int i = 0; i < 2; i++)
#pragma unroll
        for (int j = 0; j < 2; j++) wmma::fill_fragment(c[i][j], 0.0f);

    issue(0);
    issue(1);

    for (int kt = 0; kt < 32; kt++) {
        if (kt == 31) cp_wait0(); else cp_wait1();
        __syncthreads();
        if (kt + 2 < 32) issue(kt + 2);

        const float* As = reinterpret_cast<const float*>(smc + (kt % 3) * STAGE_BYTES);
        const float* Bs = reinterpret_cast<const float*>(smc + (kt % 3) * STAGE_BYTES + 20480);
#pragma unroll
        for (int ks = 0; ks < 4; ks++) {
            FragA a[2];
            FragB b[2];
#pragma unroll
            for (int i = 0; i < 2; i++)
                wmma::load_matrix_sync(a[i], As + (wrow + i * 16) * A_LD + ks * 8, A_LD);
#pragma unroll
            for (int j = 0; j < 2; j++)
                wmma::load_matrix_sync(b[j], Bs + (ks * 8) * B_LD + wcol + j * 16, B_LD);
#pragma unroll
            for (int i = 0; i < 2; i++)
#pragma unroll
                for (int j = 0; j < 2; j++)
                    wmma::mma_sync(c[i][j], a[i], b[j], c[i][j]);
        }
    }

    __syncthreads();
    float* Cs = reinterpret_cast<float*>(smc);
#pragma unroll
    for (int i = 0; i < 2; i++)
#pragma unroll
        for (int j = 0; j < 2; j++)
            wmma::store_matrix_sync(Cs + (wrow + i * 16) * C_LD + wcol + j * 16,
                                    c[i][j], C_LD, wmma::mem_row_major);
    __syncthreads();

#pragma unroll
    for (int i = 0; i < 8; i++) {
        const int f = tid + i * 256;
        const int r = f >> 4;
        const int c4 = (f & 15) * 4;
        float4 v = *reinterpret_cast<const float4*>(Cs + r * C_LD + c4);
        v.x += gbias[c4 + 0];
        v.y += gbias[c4 + 1];
        v.z += gbias[c4 + 2];
        v.w += gbias[c4 + 3];
        *reinterpret_cast<float4*>(out + (size_t)(m0 + r) * EE + n0 + c4) = v;
    }
}

// ---------------------------------------------------------------------------
// Kernel 2: FA2-style flash attention with raw mma.sync (tf32).
// CTA = 64 queries x (bh). 128 threads = 4 warps, each warp owns 16 q-rows.
// K/V tiles of 64 keys, 3-stage cp.async, ONE __syncthreads per tile.
// S, P, O all register-resident; P relaid C->A frag via shuffles.
// Gate folded into epilogue (g_attn = gate[h] * attn).
// K smem stride 68 floats (bank-clean for S B-frags);
// V smem stride 72 floats (bank-clean for PV B-frags).
// ---------------------------------------------------------------------------
#define K_LDS 68
#define V_LDS 72
#define KBYTES (64 * K_LDS * 4)     // 17408
#define VBYTES (64 * V_LDS * 4)     // 18432
#define ATTN_STAGE (KBYTES + VBYTES)
#define ATTN_SMEM (3 * ATTN_STAGE)  // 107520

__global__ __launch_bounds__(128) void flash_attn_tc2(const float* __restrict__ gate)
{
    extern __shared__ char smc[];
    const uint32_t smb = smem_u32(smc);

    const int bh = blockIdx.y;
    const int q0 = blockIdx.x * 64;
    const int tid  = threadIdx.x;
    const int wid  = tid >> 5;
    const int lane = tid & 31;
    const int qq   = lane & 3;      // quad position
    const int lr   = lane >> 2;     // 0..7
    const int wrow = wid * 16;

    const float* Qg = g_Q + ((size_t)bh * TT) * DD;
    const float* Kg = g_K + (size_t)bh * TT * DD;
    const float* Vg = g_V + (size_t)bh * TT * DD;

    // --- Load Q A-fragments into registers (pre-scaled by 1/sqrt(D)) ---
    uint32_t qa[8][4];
    {
        const int r0 = q0 + wrow + lr;
        const float scale = 0.125f;
#pragma unroll
        for (int kc = 0; kc < 8; kc++) {
            const int col = kc * 8 + qq;
            qa[kc][0] = __float_as_uint(Qg[(size_t)r0 * DD + col] * scale);
            qa[kc][1] = __float_as_uint(Qg[(size_t)(r0 + 8) * DD + col] * scale);
            qa[kc][2] = __float_as_uint(Qg[(size_t)r0 * DD + col + 4] * scale);
            qa[kc][3] = __float_as_uint(Qg[(size_t)(r0 + 8) * DD + col + 4] * scale);
        }
    }

    // stage issue: K tile + V tile for key block kb into stage kb%3
    auto issue = [&](int kb) {
        const uint32_t Ku = smb + (kb % 3) * ATTN_STAGE;
        const uint32_t Vu = Ku + KBYTES;
        const float* Ksrc = Kg + (size_t)(kb * 64) * DD;
        const float* Vsrc = Vg + (size_t)(kb * 64) * DD;
#pragma unroll
        for (int i = 0; i < 8; i++) {
            const int ch = tid + i * 128;       // 0..1023
            const int r = ch >> 4, cc = ch & 15;
            cp16(Ku + r * (K_LDS * 4) + cc * 16, Ksrc + (size_t)r * DD + cc * 4);
        }
#pragma unroll
        for (int i = 0; i < 8; i++) {
            const int ch = tid + i * 128;
            const int r = ch >> 4, cc = ch & 15;
            cp16(Vu + r * (V_LDS * 4) + cc * 16, Vsrc + (size_t)r * DD + cc * 4);
        }
        cp_commit();
    };

    float oc[8][4];
#pragma unroll
    for (int j = 0; j < 8; j++)
#pragma unroll
        for (int k = 0; k < 4; k++) oc[j][k] = 0.f;
    float m0 = -1e30f, m1 = -1e30f, l0 = 0.f, l1 = 0.f;

    issue(0);
    issue(1);

    for (int kb = 0; kb < TT / 64; kb++) {
        if (kb == TT / 64 - 1) cp_wait0(); else cp_wait1();
        __syncthreads();
        if (kb + 2 < TT / 64) issue(kb + 2);

        const float* Ks = reinterpret_cast<const float*>(smc + (kb % 3) * ATTN_STAGE);
        const float* Vs = reinterpret_cast<const float*>(smc + (kb % 3) * ATTN_STAGE + KBYTES);

        // ---- S = Q K^T (16 x 64 per warp), register C frags ----
        float sc[8][4];
#pragma unroll
        for (int j = 0; j < 8; j++)
#pragma unroll
            for (int k = 0; k < 4; k++) sc[j][k] = 0.f;

#pragma unroll
        for (int kc = 0; kc < 8; kc++) {
#pragma unroll
            for (int j = 0; j < 8; j++) {
                const float* kp = Ks + (j * 8 + lr) * K_LDS + kc * 8 + qq;
                uint32_t b[2];
                b[0] = __float_as_uint(kp[0]);
                b[1] = __float_as_uint(kp[4]);
                mma_tf32(sc[j], qa[kc], b, sc[j]);
            }
        }

        // ---- Online softmax on registers ----
        float mx0 = -1e30f, mx1 = -1e30f;
#pragma unroll
        for (int j = 0; j < 8; j++) {
            mx0 = fmaxf(mx0, fmaxf(sc[j][0], sc[j][1]));
            mx1 = fmaxf(mx1, fmaxf(sc[j][2], sc[j][3]));
        }
        mx0 = fmaxf(mx0, __shfl_xor_sync(0xffffffffu, mx0, 1));
        mx0 = fmaxf(mx0, __shfl_xor_sync(0xffffffffu, mx0, 2));
        mx1 = fmaxf(mx1, __shfl_xor_sync(0xffffffffu, mx1, 1));
        mx1 = fmaxf(mx1, __shfl_xor_sync(0xffffffffu, mx1, 2));

        const float mn0 = fmaxf(m0, mx0);
        const float mn1 = fmaxf(m1, mx1);
        const float al0 = __expf(m0 - mn0);
        const float al1 = __expf(m1 - mn1);

        float s0 = 0.f, s1 = 0.f;
#pragma unroll
        for (int j = 0; j < 8; j++) {
            sc[j][0] = __expf(sc[j][0] - mn0);
            sc[j][1] = __expf(sc[j][1] - mn0);
            sc[j][2] = __expf(sc[j][2] - mn1);
            sc[j][3] = __expf(sc[j][3] - mn1);
            s0 += sc[j][0] + sc[j][1];
            s1 += sc[j][2] + sc[j][3];
        }
        s0 += __shfl_xor_sync(0xffffffffu, s0, 1);
        s0 += __shfl_xor_sync(0xffffffffu, s0, 2);
        s1 += __shfl_xor_sync(0xffffffffu, s1, 1);
        s1 += __shfl_xor_sync(0xffffffffu, s1, 2);

        l0 = l0 * al0 + s0;
        l1 = l1 * al1 + s1;
        m0 = mn0;
        m1 = mn1;

#pragma unroll
        for (int j = 0; j < 8; j++) {
            oc[j][0] *= al0;
            oc[j][1] *= al0;
            oc[j][2] *= al1;
            oc[j][3] *= al1;
        }

        // ---- O += P V : relay P C-frag -> A-frag via quad shuffles ----
        const int src_a = (lane & 28) | (qq >> 1);
        const int src_b = src_a + 2;
#pragma unroll
        for (int kc2 = 0; kc2 < 8; kc2++) {
            const float x0 = __shfl_sync(0xffffffffu, sc[kc2][0], src_a);
            const float x1 = __shfl_sync(0xffffffffu, sc[kc2][1], src_a);
            const float y0 = __shfl_sync(0xffffffffu, sc[kc2][2], src_a);
            const float y1 = __shfl_sync(0xffffffffu, sc[kc2][3], src_a);
            const float z0 = __shfl_sync(0xffffffffu, sc[kc2][0], src_b);
            const float z1 = __shfl_sync(0xffffffffu, sc[kc2][1], src_b);
            const float w0 = __shfl_sync(0xffffffffu, sc[kc2][2], src_b);
            const float w1 = __shfl_sync(0xffffffffu, sc[kc2][3], src_b);
            uint32_t pa[4];
            pa[0] = __float_as_uint((qq & 1) ? x1 : x0);
            pa[1] = __float_as_uint((qq & 1) ? y1 : y0);
            pa[2] = __float_as_uint((qq & 1) ? z1 : z0);
            pa[3] = __float_as_uint((qq & 1) ? w1 : w0);
#pragma unroll
            for (int j = 0; j < 8; j++) {
                const float* vp = Vs + (kc2 * 8 + qq) * V_LDS + j * 8 + lr;
                uint32_t b[2];
                b[0] = __float_as_uint(vp[0]);
                b[1] = __float_as_uint(vp[4 * V_LDS]);
                mma_tf32(oc[j], pa, b, oc[j]);
            }
        }
    }

    // ---- Epilogue: normalize, apply gate, write g_attn ----
    const int b  = bh >> 4;
    const int h  = bh & 15;
    const float g = gate[h];
    const float inv0 = g / l0;
    const float inv1 = g / l1;
    const int r0 = q0 + wrow + lr;
    float* row0 = g_attn + ((size_t)(b * TT + r0)) * EE + h * DD;
    float* row1 = g_attn + ((size_t)(b * TT + r0 + 8)) * EE + h * DD;
#pragma unroll
    for (int j = 0; j < 8; j++) {
        const int col = j * 8 + 2 * qq;
        float2 v0 = make_float2(oc[j][0] * inv0, oc[j][1] * inv0);
        float2 v1 = make_float2(oc[j][2] * inv1, oc[j][3] * inv1);
        *reinterpret_cast<float2*>(row0 + col) = v0;
        *reinterpret_cast<float2*>(row1 + col) = v1;
    }
}

// ---------------------------------------------------------------------------
extern "C" void kernel_launch(void* const* d_in, const int* in_sizes, int n_in,
                              void* d_out, int out_size)
{
    const float* X    = (const float*)d_in[0];
    const float* Wq   = (const float*)d_in[1];
    const float* bq   = (const float*)d_in[2];
    const float* Wk   = (const float*)d_in[3];
    const float* bk   = (const float*)d_in[4];
    const float* Wv   = (const float*)d_in[5];
    const float* bv   = (const float*)d_in[6];
    const float* Wo   = (const float*)d_in[7];
    const float* bo   = (const float*)d_in[8];
    const float* gate = (const float*)d_in[9];
    float* out = (float*)d_out;

    cudaFuncSetAttribute(qkv_gemm_tc,   cudaFuncAttributeMaxDynamicSharedMemorySize, GEMM_SMEM);
    cudaFuncSetAttribute(out_gemm_tc,   cudaFuncAttributeMaxDynamicSharedMemorySize, GEMM_SMEM);
    cudaFuncSetAttribute(flash_attn_tc2, cudaFuncAttributeMaxDynamicSharedMemorySize, ATTN_SMEM);

    qkv_gemm_tc<<<dim3(48, MM / 128), 256, GEMM_SMEM>>>(X, Wq, bq, Wk, bk, Wv, bv);
    flash_attn_tc2<<<dim3(TT / 64, BH), 128, ATTN_SMEM>>>(gate);
    out_gemm_tc<<<dim3(EE / 64, MM / 128), 256, GEMM_SMEM>>>(Wo, bo, gate, out);
}

// round 5
// speedup vs baseline: 2.6056x; 1.0402x over previous
#include <cuda_runtime.h>
#include <mma.h>
#include <cstdint>
#include <math.h>

using namespace nvcuda;

// ---------------------------------------------------------------------------
// Problem constants
// ---------------------------------------------------------------------------
#define BB 2
#define TT 2048
#define EE 1024
#define HH 16
#define DD 64
#define MM (BB * TT)
#define BH (BB * HH)

// Scratch (device globals; allocation-free)
__device__ float g_Q[BH * TT * DD];
__device__ float g_K[BH * TT * DD];
__device__ float g_V[BH * TT * DD];
__device__ float g_attn[MM * EE];   // gated attention output, [b*T+t, h*64+d]

// ---------------------------------------------------------------------------
// Helpers
// ---------------------------------------------------------------------------
__device__ __forceinline__ uint32_t smem_u32(const void* p) {
    return (uint32_t)__cvta_generic_to_shared(p);
}
__device__ __forceinline__ void cp16(uint32_t dst, const void* src) {
    asm volatile("cp.async.cg.shared.global [%0], [%1], 16;\n" :: "r"(dst), "l"(src));
}
__device__ __forceinline__ void cp_commit() {
    asm volatile("cp.async.commit_group;\n" ::: "memory");
}
__device__ __forceinline__ void cp_wait1() {
    asm volatile("cp.async.wait_group 1;\n" ::: "memory");
}
__device__ __forceinline__ void cp_wait0() {
    asm volatile("cp.async.wait_group 0;\n" ::: "memory");
}

// m16n8k8 tf32 mma (HW truncates fp32 operands to tf32)
__device__ __forceinline__ void mma_tf32(float* d, const uint32_t* a,
                                         const uint32_t* b, const float* c) {
    asm volatile(
        "mma.sync.aligned.m16n8k8.row.col.f32.tf32.tf32.f32 "
        "{%0,%1,%2,%3}, {%4,%5,%6,%7}, {%8,%9}, {%10,%11,%12,%13};\n"
        : "=f"(d[0]), "=f"(d[1]), "=f"(d[2]), "=f"(d[3])
        : "r"(a[0]), "r"(a[1]), "r"(a[2]), "r"(a[3]),
          "r"(b[0]), "r"(b[1]),
          "f"(c[0]), "f"(c[1]), "f"(c[2]), "f"(c[3]));
}

typedef wmma::fragment<wmma::matrix_a, 16, 16, 8, wmma::precision::tf32, wmma::row_major> FragA;
typedef wmma::fragment<wmma::matrix_b, 16, 16, 8, wmma::precision::tf32, wmma::row_major> FragB;
typedef wmma::fragment<wmma::accumulator, 16, 16, 8, float> FragC;

// ---------------------------------------------------------------------------
// GEMM smem: 3 stages of (A 128x40 fp32 = 20480 B, B 32x136 fp32 = 17408 B)
// Stage = 37888 B, total 113664 B. C epilogue (128x136 = 69632 B) overlays.
// CTA tile 128x128, 8 warps, warp tile 32x64 (4 row-groups x 2 col-groups).
// ---------------------------------------------------------------------------
#define A_LD 40
#define B_LD 136
#define C_LD 136
#define STAGE_BYTES 37888
#define GEMM_SMEM (3 * STAGE_BYTES)

// ---------------------------------------------------------------------------
// Kernel 1: fused QKV projection. grid (24, 32): n0 = bx*128 in [0,3072),
// covers 2 heads of one of Q/K/V.
// ---------------------------------------------------------------------------
__global__ __launch_bounds__(256, 2) void qkv_gemm_tc(
    const float* __restrict__ X,
    const float* __restrict__ Wq, const float* __restrict__ bq,
    const float* __restrict__ Wk, const float* __restrict__ bk,
    const float* __restrict__ Wv, const float* __restrict__ bv)
{
    extern __shared__ char smc[];
    const uint32_t smb = smem_u32(smc);

    const int n0  = blockIdx.x * 128;
    const int m0  = blockIdx.y * 128;
    const int mat = n0 >> 10;
    const int h0  = (n0 & 1023) >> 6;   // first of two heads

    const float* W    = (mat == 0 ? Wq : (mat == 1 ? Wk : Wv));
    const float* bias = (mat == 0 ? bq : (mat == 1 ? bk : bv));
    float* dst        = (mat == 0 ? g_Q : (mat == 1 ? g_K : g_V));

    const int tid = threadIdx.x;
    const int wid = tid >> 5;
    const int wrow = (wid & 3) * 32;    // 0,32,64,96
    const int wcol = (wid >> 2) * 64;   // 0,64

    auto issue = [&](int kt) {
        const int k0 = kt * 32;
        const uint32_t Au = smb + (kt % 3) * STAGE_BYTES;
        const uint32_t Bu = Au + 20480;
        // A: 128x32 = 1024 float4
#pragma unroll
        for (int i = 0; i < 4; i++) {
            const int ch = tid + i * 256;
            const int r = ch >> 3, c = ch & 7;
            cp16(Au + r * (A_LD * 4) + c * 16, X + (size_t)(m0 + r) * EE + k0 + c * 4);
        }
        // B: 32 rows x 128 cols = 1024 float4; col group c -> head h0 + (c>>4)
#pragma unroll
        for (int i = 0; i < 4; i++) {
            const int ch = tid + i * 256;
            const int r = ch >> 5, c = ch & 31;
            const int h = h0 + (c >> 4);
            const int d = (c * 4) & 63;
            cp16(Bu + r * (B_LD * 4) + c * 16,
                 W + ((size_t)h * EE + k0 + r) * DD + d);
        }
        cp_commit();
    };

    FragC c[2][4];
#pragma unroll
    for (int i = 0; i < 2; i++)
#pragma unroll
        for (int j = 0; j < 4; j++) wmma::fill_fragment(c[i][j], 0.0f);

    issue(0);
    issue(1);

    for (int kt = 0; kt < 32; kt++) {
        if (kt == 31) cp_wait0(); else cp_wait1();
        __syncthreads();
        if (kt + 2 < 32) issue(kt + 2);

        const float* As = reinterpret_cast<const float*>(smc + (kt % 3) * STAGE_BYTES);
        const float* Bs = reinterpret_cast<const float*>(smc + (kt % 3) * STAGE_BYTES + 20480);
#pragma unroll
        for (int ks = 0; ks < 4; ks++) {
            FragA a[2];
            FragB b[4];
#pragma unroll
            for (int i = 0; i < 2; i++)
                wmma::load_matrix_sync(a[i], As + (wrow + i * 16) * A_LD + ks * 8, A_LD);
#pragma unroll
            for (int j = 0; j < 4; j++)
                wmma::load_matrix_sync(b[j], Bs + (ks * 8) * B_LD + wcol + j * 16, B_LD);
#pragma unroll
            for (int i = 0; i < 2; i++)
#pragma unroll
                for (int j = 0; j < 4; j++)
                    wmma::mma_sync(c[i][j], a[i], b[j], c[i][j]);
        }
    }

    __syncthreads();
    float* Cs = reinterpret_cast<float*>(smc);
#pragma unroll
    for (int i = 0; i < 2; i++)
#pragma unroll
        for (int j = 0; j < 4; j++)
            wmma::store_matrix_sync(Cs + (wrow + i * 16) * C_LD + wcol + j * 16,
                                    c[i][j], C_LD, wmma::mem_row_major);
    __syncthreads();

    // Epilogue: 128x128 outputs = 4096 float4, 16 per thread
#pragma unroll
    for (int i = 0; i < 16; i++) {
        const int f = tid + i * 256;
        const int r = f >> 5;
        const int c4 = (f & 31) * 4;
        const int m  = m0 + r;
        const int bb = m >> 11;
        const int t  = m & (TT - 1);
        const int h  = h0 + (c4 >> 6);
        const int d  = c4 & 63;
        const float* bp = bias + h * DD + d;
        float4 v = *reinterpret_cast<const float4*>(Cs + r * C_LD + c4);
        v.x += bp[0];
        v.y += bp[1];
        v.z += bp[2];
        v.w += bp[3];
        *reinterpret_cast<float4*>(dst + ((size_t)((bb * HH + h) * TT + t)) * DD + d) = v;
    }
}

// ---------------------------------------------------------------------------
// Kernel 3: output projection. grid (8, 32). CTA tile 128x128.
// A = g_attn (already gated in attention epilogue), B = Wo; gated bias.
// ---------------------------------------------------------------------------
__global__ __launch_bounds__(256, 2) void out_gemm_tc(
    const float* __restrict__ Wo, const float* __restrict__ bo,
    const float* __restrict__ gate, float* __restrict__ out)
{
    extern __shared__ char smc[];
    const uint32_t smb = smem_u32(smc);
    __shared__ float gbias[128];

    const int n0 = blockIdx.x * 128;
    const int m0 = blockIdx.y * 128;

    const int tid = threadIdx.x;
    const int wid = tid >> 5;
    const int wrow = (wid & 3) * 32;
    const int wcol = (wid >> 2) * 64;

    if (tid < 128) {
        float s = 0.f;
#pragma unroll
        for (int hh = 0; hh < HH; hh++)
            s = fmaf(gate[hh], bo[(size_t)hh * EE + n0 + tid], s);
        gbias[tid] = s;
    }

    auto issue = [&](int kt) {
        const int k0 = kt * 32;
        const uint32_t Au = smb + (kt % 3) * STAGE_BYTES;
        const uint32_t Bu = Au + 20480;
#pragma unroll
        for (int i = 0; i < 4; i++) {
            const int ch = tid + i * 256;
            const int r = ch >> 3, c = ch & 7;
            cp16(Au + r * (A_LD * 4) + c * 16, g_attn + (size_t)(m0 + r) * EE + k0 + c * 4);
        }
#pragma unroll
        for (int i = 0; i < 4; i++) {
            const int ch = tid + i * 256;
            const int r = ch >> 5, c = ch & 31;
            cp16(Bu + r * (B_LD * 4) + c * 16, Wo + (size_t)(k0 + r) * EE + n0 + c * 4);
        }
        cp_commit();
    };

    FragC c[2][4];
#pragma unroll
    for (int i = 0; i < 2; i++)
#pragma unroll
        for (int j = 0; j < 4; j++) wmma::fill_fragment(c[i][j], 0.0f);

    issue(0);
    issue(1);

    for (int kt = 0; kt < 32; kt++) {
        if (kt == 31) cp_wait0(); else cp_wait1();
        __syncthreads();
        if (kt + 2 < 32) issue(kt + 2);

        const float* As = reinterpret_cast<const float*>(smc + (kt % 3) * STAGE_BYTES);
        const float* Bs = reinterpret_cast<const float*>(smc + (kt % 3) * STAGE_BYTES + 20480);
#pragma unroll
        for (int ks = 0; ks < 4; ks++) {
            FragA a[2];
            FragB b[4];
#pragma unroll
            for (int i = 0; i < 2; i++)
                wmma::load_matrix_sync(a[i], As + (wrow + i * 16) * A_LD + ks * 8, A_LD);
#pragma unroll
            for (int j = 0; j < 4; j++)
                wmma::load_matrix_sync(b[j], Bs + (ks * 8) * B_LD + wcol + j * 16, B_LD);
#pragma unroll
            for (int i = 0; i < 2; i++)
#pragma unroll
                for (int j = 0; j < 4; j++)
                    wmma::mma_sync(c[i][j], a[i], b[j], c[i][j]);
        }
    }

    __syncthreads();
    float* Cs = reinterpret_cast<float*>(smc);
#pragma unroll
    for (int i = 0; i < 2; i++)
#pragma unroll
        for (int j = 0; j < 4; j++)
            wmma::store_matrix_sync(Cs + (wrow + i * 16) * C_LD + wcol + j * 16,
                                    c[i][j], C_LD, wmma::mem_row_major);
    __syncthreads();

#pragma unroll
    for (int i = 0; i < 16; i++) {
        const int f = tid + i * 256;
        const int r = f >> 5;
        const int c4 = (f & 31) * 4;
        float4 v = *reinterpret_cast<const float4*>(Cs + r * C_LD + c4);
        v.x += gbias[c4 + 0];
        v.y += gbias[c4 + 1];
        v.z += gbias[c4 + 2];
        v.w += gbias[c4 + 3];
        *reinterpret_cast<float4*>(out + (size_t)(m0 + r) * EE + n0 + c4) = v;
    }
}

// ---------------------------------------------------------------------------
// Kernel 2: FA2-style flash attention (tf32 mma.sync).
// CTA = 128 queries x (bh). 256 threads = 8 warps, each warp owns 16 q-rows.
// K/V tiles of 64 keys, 3-stage cp.async, one __syncthreads per tile.
// ---------------------------------------------------------------------------
#define K_LDS 68
#define V_LDS 72
#define KBYTES (64 * K_LDS * 4)
#define VBYTES (64 * V_LDS * 4)
#define ATTN_STAGE (KBYTES + VBYTES)
#define ATTN_SMEM (3 * ATTN_STAGE)

__global__ __launch_bounds__(256, 2) void flash_attn_tc2(const float* __restrict__ gate)
{
    extern __shared__ char smc[];
    const uint32_t smb = smem_u32(smc);

    const int bh = blockIdx.y;
    const int q0 = blockIdx.x * 128;
    const int tid  = threadIdx.x;
    const int wid  = tid >> 5;
    const int lane = tid & 31;
    const int qq   = lane & 3;
    const int lr   = lane >> 2;
    const int wrow = wid * 16;

    const float* Qg = g_Q + ((size_t)bh * TT) * DD;
    const float* Kg = g_K + (size_t)bh * TT * DD;
    const float* Vg = g_V + (size_t)bh * TT * DD;

    // Q A-fragments (pre-scaled by 1/sqrt(D))
    uint32_t qa[8][4];
    {
        const int r0 = q0 + wrow + lr;
        const float scale = 0.125f;
#pragma unroll
        for (int kc = 0; kc < 8; kc++) {
            const int col = kc * 8 + qq;
            qa[kc][0] = __float_as_uint(Qg[(size_t)r0 * DD + col] * scale);
            qa[kc][1] = __float_as_uint(Qg[(size_t)(r0 + 8) * DD + col] * scale);
            qa[kc][2] = __float_as_uint(Qg[(size_t)r0 * DD + col + 4] * scale);
            qa[kc][3] = __float_as_uint(Qg[(size_t)(r0 + 8) * DD + col + 4] * scale);
        }
    }

    auto issue = [&](int kb) {
        const uint32_t Ku = smb + (kb % 3) * ATTN_STAGE;
        const uint32_t Vu = Ku + KBYTES;
        const float* Ksrc = Kg + (size_t)(kb * 64) * DD;
        const float* Vsrc = Vg + (size_t)(kb * 64) * DD;
#pragma unroll
        for (int i = 0; i < 4; i++) {
            const int ch = tid + i * 256;
            const int r = ch >> 4, cc = ch & 15;
            cp16(Ku + r * (K_LDS * 4) + cc * 16, Ksrc + (size_t)r * DD + cc * 4);
        }
#pragma unroll
        for (int i = 0; i < 4; i++) {
            const int ch = tid + i * 256;
            const int r = ch >> 4, cc = ch & 15;
            cp16(Vu + r * (V_LDS * 4) + cc * 16, Vsrc + (size_t)r * DD + cc * 4);
        }
        cp_commit();
    };

    float oc[8][4];
#pragma unroll
    for (int j = 0; j < 8; j++)
#pragma unroll
        for (int k = 0; k < 4; k++) oc[j][k] = 0.f;
    float m0 = -1e30f, m1 = -1e30f, l0 = 0.f, l1 = 0.f;

    issue(0);
    issue(1);

    for (int kb = 0; kb < TT / 64; kb++) {
        if (kb == TT / 64 - 1) cp_wait0(); else cp_wait1();
        __syncthreads();
        if (kb + 2 < TT / 64) issue(kb + 2);

        const float* Ks = reinterpret_cast<const float*>(smc + (kb % 3) * ATTN_STAGE);
        const float* Vs = reinterpret_cast<const float*>(smc + (kb % 3) * ATTN_STAGE + KBYTES);

        // ---- S = Q K^T (16 x 64 per warp) ----
        float sc[8][4];
#pragma unroll
        for (int j = 0; j < 8; j++)
#pragma unroll
            for (int k = 0; k < 4; k++) sc[j][k] = 0.f;

#pragma unroll
        for (int kc = 0; kc < 8; kc++) {
#pragma unroll
            for (int j = 0; j < 8; j++) {
                const float* kp = Ks + (j * 8 + lr) * K_LDS + kc * 8 + qq;
                uint32_t b[2];
                b[0] = __float_as_uint(kp[0]);
                b[1] = __float_as_uint(kp[4]);
                mma_tf32(sc[j], qa[kc], b, sc[j]);
            }
        }

        // ---- Online softmax ----
        float mx0 = -1e30f, mx1 = -1e30f;
#pragma unroll
        for (int j = 0; j < 8; j++) {
            mx0 = fmaxf(mx0, fmaxf(sc[j][0], sc[j][1]));
            mx1 = fmaxf(mx1, fmaxf(sc[j][2], sc[j][3]));
        }
        mx0 = fmaxf(mx0, __shfl_xor_sync(0xffffffffu, mx0, 1));
        mx0 = fmaxf(mx0, __shfl_xor_sync(0xffffffffu, mx0, 2));
        mx1 = fmaxf(mx1, __shfl_xor_sync(0xffffffffu, mx1, 1));
        mx1 = fmaxf(mx1, __shfl_xor_sync(0xffffffffu, mx1, 2));

        const float mn0 = fmaxf(m0, mx0);
        const float mn1 = fmaxf(m1, mx1);
        const float al0 = __expf(m0 - mn0);
        const float al1 = __expf(m1 - mn1);

        float s0 = 0.f, s1 = 0.f;
#pragma unroll
        for (int j = 0; j < 8; j++) {
            sc[j][0] = __expf(sc[j][0] - mn0);
            sc[j][1] = __expf(sc[j][1] - mn0);
            sc[j][2] = __expf(sc[j][2] - mn1);
            sc[j][3] = __expf(sc[j][3] - mn1);
            s0 += sc[j][0] + sc[j][1];
            s1 += sc[j][2] + sc[j][3];
        }
        s0 += __shfl_xor_sync(0xffffffffu, s0, 1);
        s0 += __shfl_xor_sync(0xffffffffu, s0, 2);
        s1 += __shfl_xor_sync(0xffffffffu, s1, 1);
        s1 += __shfl_xor_sync(0xffffffffu, s1, 2);

        l0 = l0 * al0 + s0;
        l1 = l1 * al1 + s1;
        m0 = mn0;
        m1 = mn1;

#pragma unroll
        for (int j = 0; j < 8; j++) {
            oc[j][0] *= al0;
            oc[j][1] *= al0;
            oc[j][2] *= al1;
            oc[j][3] *= al1;
        }

        // ---- O += P V (P relaid C->A frag via quad shuffles) ----
        const int src_a = (lane & 28) | (qq >> 1);
        const int src_b = src_a + 2;
#pragma unroll
        for (int kc2 = 0; kc2 < 8; kc2++) {
            const float x0 = __shfl_sync(0xffffffffu, sc[kc2][0], src_a);
            const float x1 = __shfl_sync(0xffffffffu, sc[kc2][1], src_a);
            const float y0 = __shfl_sync(0xffffffffu, sc[kc2][2], src_a);
            const float y1 = __shfl_sync(0xffffffffu, sc[kc2][3], src_a);
            const float z0 = __shfl_sync(0xffffffffu, sc[kc2][0], src_b);
            const float z1 = __shfl_sync(0xffffffffu, sc[kc2][1], src_b);
            const float w0 = __shfl_sync(0xffffffffu, sc[kc2][2], src_b);
            const float w1 = __shfl_sync(0xffffffffu, sc[kc2][3], src_b);
            uint32_t pa[4];
            pa[0] = __float_as_uint((qq & 1) ? x1 : x0);
            pa[1] = __float_as_uint((qq & 1) ? y1 : y0);
            pa[2] = __float_as_uint((qq & 1) ? z1 : z0);
            pa[3] = __float_as_uint((qq & 1) ? w1 : w0);
#pragma unroll
            for (int j = 0; j < 8; j++) {
                const float* vp = Vs + (kc2 * 8 + qq) * V_LDS + j * 8 + lr;
                uint32_t b[2];
                b[0] = __float_as_uint(vp[0]);
                b[1] = __float_as_uint(vp[4 * V_LDS]);
                mma_tf32(oc[j], pa, b, oc[j]);
            }
        }
    }

    // ---- Epilogue: normalize, apply gate, write g_attn ----
    const int b  = bh >> 4;
    const int h  = bh & 15;
    const float g = gate[h];
    const float inv0 = g / l0;
    const float inv1 = g / l1;
    const int r0 = q0 + wrow + lr;
    float* row0 = g_attn + ((size_t)(b * TT + r0)) * EE + h * DD;
    float* row1 = g_attn + ((size_t)(b * TT + r0 + 8)) * EE + h * DD;
#pragma unroll
    for (int j = 0; j < 8; j++) {
        const int col = j * 8 + 2 * qq;
        float2 v0 = make_float2(oc[j][0] * inv0, oc[j][1] * inv0);
        float2 v1 = make_float2(oc[j][2] * inv1, oc[j][3] * inv1);
        *reinterpret_cast<float2*>(row0 + col) = v0;
        *reinterpret_cast<float2*>(row1 + col) = v1;
    }
}

// ---------------------------------------------------------------------------
extern "C" void kernel_launch(void* const* d_in, const int* in_sizes, int n_in,
                              void* d_out, int out_size)
{
    const float* X    = (const float*)d_in[0];
    const float* Wq   = (const float*)d_in[1];
    const float* bq   = (const float*)d_in[2];
    const float* Wk   = (const float*)d_in[3];
    const float* bk   = (const float*)d_in[4];
    const float* Wv   = (const float*)d_in[5];
    const float* bv   = (const float*)d_in[6];
    const float* Wo   = (const float*)d_in[7];
    const float* bo   = (const float*)d_in[8];
    const float* gate = (const float*)d_in[9];
    float* out = (float*)d_out;

    cudaFuncSetAttribute(qkv_gemm_tc,    cudaFuncAttributeMaxDynamicSharedMemorySize, GEMM_SMEM);
    cudaFuncSetAttribute(out_gemm_tc,    cudaFuncAttributeMaxDynamicSharedMemorySize, GEMM_SMEM);
    cudaFuncSetAttribute(flash_attn_tc2, cudaFuncAttributeMaxDynamicSharedMemorySize, ATTN_SMEM);

    qkv_gemm_tc<<<dim3(3072 / 128, MM / 128), 256, GEMM_SMEM>>>(X, Wq, bq, Wk, bk, Wv, bv);
    flash_attn_tc2<<<dim3(TT / 128, BH), 256, ATTN_SMEM>>>(gate);
    out_gemm_tc<<<dim3(EE / 128, MM / 128), 256, GEMM_SMEM>>>(Wo, bo, gate, out);
}

// round 6
// speedup vs baseline: 3.5790x; 1.3736x over previous
#include <cuda_runtime.h>
#include <cstdint>
#include <math.h>

// ---------------------------------------------------------------------------
// Problem constants
// ---------------------------------------------------------------------------
#define BB 2
#define TT 2048
#define EE 1024
#define HH 16
#define DD 64
#define MM (BB * TT)
#define BH (BB * HH)

// Scratch (device globals; allocation-free)
__device__ float g_Q[BH * TT * DD];           // [bh][t][d]
__device__ float g_K[BH * TT * DD];           // [bh][t][d]
__device__ float g_V[BH * TT * DD];           // [bh][d][t]  (TRANSPOSED)
__device__ float g_attn[MM * EE];             // gated attn out [b*T+t][h*64+d]
__device__ float g_Wt[3 * EE * EE];           // [mat][n=h*64+d][e]
__device__ float g_Wot[EE * EE];              // [n=e][k=h*64+d]

// ---------------------------------------------------------------------------
// Helpers
// ---------------------------------------------------------------------------
__device__ __forceinline__ uint32_t smem_u32(const void* p) {
    return (uint32_t)__cvta_generic_to_shared(p);
}
__device__ __forceinline__ void cp16(uint32_t dst, const void* src) {
    asm volatile("cp.async.cg.shared.global [%0], [%1], 16;\n" :: "r"(dst), "l"(src));
}
__device__ __forceinline__ void cp_commit() {
    asm volatile("cp.async.commit_group;\n" ::: "memory");
}
__device__ __forceinline__ void cp_wait1() {
    asm volatile("cp.async.wait_group 1;\n" ::: "memory");
}
__device__ __forceinline__ void cp_wait0() {
    asm volatile("cp.async.wait_group 0;\n" ::: "memory");
}
__device__ __forceinline__ void ldsm4(uint32_t addr, uint32_t& r0, uint32_t& r1,
                                      uint32_t& r2, uint32_t& r3) {
    asm volatile("ldmatrix.sync.aligned.m8n8.x4.shared.b16 {%0,%1,%2,%3}, [%4];"
                 : "=r"(r0), "=r"(r1), "=r"(r2), "=r"(r3) : "r"(addr));
}

// m16n8k8 tf32 mma (HW truncates fp32 operands to tf32)
__device__ __forceinline__ void mma_tf32(float* d, const uint32_t* a,
                                         const uint32_t* b, const float* c) {
    asm volatile(
        "mma.sync.aligned.m16n8k8.row.col.f32.tf32.tf32.f32 "
        "{%0,%1,%2,%3}, {%4,%5,%6,%7}, {%8,%9}, {%10,%11,%12,%13};\n"
        : "=f"(d[0]), "=f"(d[1]), "=f"(d[2]), "=f"(d[3])
        : "r"(a[0]), "r"(a[1]), "r"(a[2]), "r"(a[3]),
          "r"(b[0]), "r"(b[1]),
          "f"(c[0]), "f"(c[1]), "f"(c[2]), "f"(c[3]));
}

// ---------------------------------------------------------------------------
// Kernel 0: tiled 2D transpose, batched. src [batch][R][C] -> dst [batch][C][R].
// ---------------------------------------------------------------------------
__global__ void transpose2d(const float* __restrict__ src, float* __restrict__ dst,
                            int R, int C)
{
    __shared__ float tile[32][33];
    const int c0 = blockIdx.x * 32;
    const int r0 = blockIdx.y * 32;
    const size_t boff = (size_t)blockIdx.z * R * C;
#pragma unroll
    for (int i = 0; i < 4; i++) {
        const int r = r0 + threadIdx.y + i * 8;
        tile[threadIdx.y + i * 8][threadIdx.x] = src[boff + (size_t)r * C + c0 + threadIdx.x];
    }
    __syncthreads();
#pragma unroll
    for (int i = 0; i < 4; i++) {
        const int c = c0 + threadIdx.y + i * 8;
        dst[boff + (size_t)c * R + r0 + threadIdx.x] = tile[threadIdx.x][threadIdx.y + i * 8];
    }
}

// ---------------------------------------------------------------------------
// GEMM smem: 3 stages of (A 128x36 fp32, B 128x36 fp32) = 36864 B/stage.
// C epilogue 128x132 overlays. CTA tile 128x128, 8 warps, warp 32x64.
// ---------------------------------------------------------------------------
#define A_LD 36
#define B_LD 36
#define C_LD 132
#define STAGE_BYTES 36864
#define GEMM_SMEM (3 * STAGE_BYTES)

// ---------------------------------------------------------------------------
// Kernel 1: fused QKV projection. grid (24, 32). B from g_Wt (n-major).
// ---------------------------------------------------------------------------
__global__ __launch_bounds__(256, 2) void qkv_gemm_tc(
    const float* __restrict__ X,
    const float* __restrict__ bq, const float* __restrict__ bk,
    const float* __restrict__ bv)
{
    extern __shared__ char smc[];
    const uint32_t smb = smem_u32(smc);

    const int n0   = blockIdx.x * 128;
    const int m0   = blockIdx.y * 128;
    const int mat  = n0 >> 10;
    const int nloc = n0 & 1023;

    const float* Wt   = g_Wt + (size_t)mat * EE * EE;
    const float* bias = (mat == 0 ? bq : (mat == 1 ? bk : bv));

    const int tid  = threadIdx.x;
    const int wid  = tid >> 5;
    const int lane = tid & 31;
    const int wrow = (wid & 3) * 32;
    const int wcol = (wid >> 2) * 64;
    const int lds_row = (lane & 7) + ((lane & 16) >> 1);
    const int lds_col = (lane & 8) * 2;

    auto issue = [&](int kt) {
        const int k0 = kt * 32;
        const uint32_t Au = smb + (kt % 3) * STAGE_BYTES;
        const uint32_t Bu = Au + 18432;
#pragma unroll
        for (int i = 0; i < 4; i++) {
            const int ch = tid + i * 256;
            const int r = ch >> 3, c = ch & 7;
            cp16(Au + r * (A_LD * 4) + c * 16, X + (size_t)(m0 + r) * EE + k0 + c * 4);
        }
#pragma unroll
        for (int i = 0; i < 4; i++) {
            const int ch = tid + i * 256;
            const int r = ch >> 3, c = ch & 7;
            cp16(Bu + r * (B_LD * 4) + c * 16, Wt + (size_t)(nloc + r) * EE + k0 + c * 4);
        }
        cp_commit();
    };

    float acc[2][8][4];
#pragma unroll
    for (int i = 0; i < 2; i++)
#pragma unroll
        for (int j = 0; j < 8; j++)
#pragma unroll
            for (int k = 0; k < 4; k++) acc[i][j][k] = 0.f;

    issue(0);
    issue(1);

    for (int kt = 0; kt < 32; kt++) {
        if (kt == 31) cp_wait0(); else cp_wait1();
        __syncthreads();
        if (kt + 2 < 32) issue(kt + 2);

        const uint32_t Au = smb + (kt % 3) * STAGE_BYTES;
        const uint32_t aoffA = Au + (wrow + lds_row) * (A_LD * 4) + lds_col;
        const uint32_t aoffB = Au + 18432 + (wcol + lds_row) * (B_LD * 4) + lds_col;

#pragma unroll
        for (int ks = 0; ks < 4; ks++) {
            uint32_t a0[4], a1[4];
            ldsm4(aoffA + ks * 32, a0[0], a0[2], a0[1], a0[3]);
            ldsm4(aoffA + 16 * (A_LD * 4) + ks * 32, a1[0], a1[2], a1[1], a1[3]);
#pragma unroll
            for (int jj = 0; jj < 4; jj++) {
                uint32_t b[4];
                ldsm4(aoffB + jj * 16 * (B_LD * 4) + ks * 32, b[0], b[1], b[2], b[3]);
                mma_tf32(acc[0][jj * 2],     a0, b,     acc[0][jj * 2]);
                mma_tf32(acc[0][jj * 2 + 1], a0, b + 2, acc[0][jj * 2 + 1]);
                mma_tf32(acc[1][jj * 2],     a1, b,     acc[1][jj * 2]);
                mma_tf32(acc[1][jj * 2 + 1], a1, b + 2, acc[1][jj * 2 + 1]);
            }
        }
    }

    __syncthreads();
    float* Cs = reinterpret_cast<float*>(smc);
#pragma unroll
    for (int i = 0; i < 2; i++)
#pragma unroll
        for (int n8 = 0; n8 < 8; n8++) {
            const int row = wrow + i * 16 + (lane >> 2);
            const int col = wcol + n8 * 8 + 2 * (lane & 3);
            *reinterpret_cast<float2*>(Cs + row * C_LD + col) =
                make_float2(acc[i][n8][0], acc[i][n8][1]);
            *reinterpret_cast<float2*>(Cs + (row + 8) * C_LD + col) =
                make_float2(acc[i][n8][2], acc[i][n8][3]);
        }
    __syncthreads();

    const int bb = m0 >> 11;
    if (mat < 2) {
        float* dst = (mat == 0 ? g_Q : g_K);
#pragma unroll
        for (int i = 0; i < 16; i++) {
            const int f = tid + i * 256;
            const int r = f >> 5;
            const int c4 = (f & 31) * 4;
            const int t = (m0 & (TT - 1)) + r;
            const int n = nloc + c4;
            const int h = n >> 6, d = n & 63;
            float4 v = *reinterpret_cast<const float4*>(Cs + r * C_LD + c4);
            v.x += bias[n + 0];
            v.y += bias[n + 1];
            v.z += bias[n + 2];
            v.w += bias[n + 3];
            *reinterpret_cast<float4*>(dst + ((size_t)((bb * HH + h) * TT + t)) * DD + d) = v;
        }
    } else {
        // V: write transposed [bh][d][t]
#pragma unroll
        for (int i = 0; i < 16; i++) {
            const int f = tid + i * 256;
            const int r = f >> 5;
            const int c4 = (f & 31) * 4;
            const int t = (m0 & (TT - 1)) + r;
            const int n = nloc + c4;
            const int h = n >> 6, d = n & 63;
            float4 v = *reinterpret_cast<const float4*>(Cs + r * C_LD + c4);
            float* base = g_V + ((size_t)(bb * HH + h) * DD + d) * TT + t;
            base[0]          = v.x + bias[n + 0];
            base[TT]         = v.y + bias[n + 1];
            base[2 * TT]     = v.z + bias[n + 2];
            base[3 * TT]     = v.w + bias[n + 3];
        }
    }
}

// ---------------------------------------------------------------------------
// Kernel 3: output projection. grid (8, 32). B from g_Wot (n-major).
// ---------------------------------------------------------------------------
__global__ __launch_bounds__(256, 2) void out_gemm_tc(
    const float* __restrict__ bo, const float* __restrict__ gate,
    float* __restrict__ out)
{
    extern __shared__ char smc[];
    const uint32_t smb = smem_u32(smc);
    __shared__ float gbias[128];

    const int n0 = blockIdx.x * 128;
    const int m0 = blockIdx.y * 128;

    const int tid  = threadIdx.x;
    const int wid  = tid >> 5;
    const int lane = tid & 31;
    const int wrow = (wid & 3) * 32;
    const int wcol = (wid >> 2) * 64;
    const int lds_row = (lane & 7) + ((lane & 16) >> 1);
    const int lds_col = (lane & 8) * 2;

    if (tid < 128) {
        float s = 0.f;
#pragma unroll
        for (int hh = 0; hh < HH; hh++)
            s = fmaf(gate[hh], bo[(size_t)hh * EE + n0 + tid], s);
        gbias[tid] = s;
    }

    auto issue = [&](int kt) {
        const int k0 = kt * 32;
        const uint32_t Au = smb + (kt % 3) * STAGE_BYTES;
        const uint32_t Bu = Au + 18432;
#pragma unroll
        for (int i = 0; i < 4; i++) {
            const int ch = tid + i * 256;
            const int r = ch >> 3, c = ch & 7;
            cp16(Au + r * (A_LD * 4) + c * 16, g_attn + (size_t)(m0 + r) * EE + k0 + c * 4);
        }
#pragma unroll
        for (int i = 0; i < 4; i++) {
            const int ch = tid + i * 256;
            const int r = ch >> 3, c = ch & 7;
            cp16(Bu + r * (B_LD * 4) + c * 16, g_Wot + (size_t)(n0 + r) * EE + k0 + c * 4);
        }
        cp_commit();
    };

    float acc[2][8][4];
#pragma unroll
    for (int i = 0; i < 2; i++)
#pragma unroll
        for (int j = 0; j < 8; j++)
#pragma unroll
            for (int k = 0; k < 4; k++) acc[i][j][k] = 0.f;

    issue(0);
    issue(1);

    for (int kt = 0; kt < 32; kt++) {
        if (kt == 31) cp_wait0(); else cp_wait1();
        __syncthreads();
        if (kt + 2 < 32) issue(kt + 2);

        const uint32_t Au = smb + (kt % 3) * STAGE_BYTES;
        const uint32_t aoffA = Au + (wrow + lds_row) * (A_LD * 4) + lds_col;
        const uint32_t aoffB = Au + 18432 + (wcol + lds_row) * (B_LD * 4) + lds_col;

#pragma unroll
        for (int ks = 0; ks < 4; ks++) {
            uint32_t a0[4], a1[4];
            ldsm4(aoffA + ks * 32, a0[0], a0[2], a0[1], a0[3]);
            ldsm4(aoffA + 16 * (A_LD * 4) + ks * 32, a1[0], a1[2], a1[1], a1[3]);
#pragma unroll
            for (int jj = 0; jj < 4; jj++) {
                uint32_t b[4];
                ldsm4(aoffB + jj * 16 * (B_LD * 4) + ks * 32, b[0], b[1], b[2], b[3]);
                mma_tf32(acc[0][jj * 2],     a0, b,     acc[0][jj * 2]);
                mma_tf32(acc[0][jj * 2 + 1], a0, b + 2, acc[0][jj * 2 + 1]);
                mma_tf32(acc[1][jj * 2],     a1, b,     acc[1][jj * 2]);
                mma_tf32(acc[1][jj * 2 + 1], a1, b + 2, acc[1][jj * 2 + 1]);
            }
        }
    }

    __syncthreads();
    float* Cs = reinterpret_cast<float*>(smc);
#pragma unroll
    for (int i = 0; i < 2; i++)
#pragma unroll
        for (int n8 = 0; n8 < 8; n8++) {
            const int row = wrow + i * 16 + (lane >> 2);
            const int col = wcol + n8 * 8 + 2 * (lane & 3);
            *reinterpret_cast<float2*>(Cs + row * C_LD + col) =
                make_float2(acc[i][n8][0], acc[i][n8][1]);
            *reinterpret_cast<float2*>(Cs + (row + 8) * C_LD + col) =
                make_float2(acc[i][n8][2], acc[i][n8][3]);
        }
    __syncthreads();

#pragma unroll
    for (int i = 0; i < 16; i++) {
        const int f = tid + i * 256;
        const int r = f >> 5;
        const int c4 = (f & 31) * 4;
        float4 v = *reinterpret_cast<const float4*>(Cs + r * C_LD + c4);
        v.x += gbias[c4 + 0];
        v.y += gbias[c4 + 1];
        v.z += gbias[c4 + 2];
        v.w += gbias[c4 + 3];
        *reinterpret_cast<float4*>(out + (size_t)(m0 + r) * EE + n0 + c4) = v;
    }
}

// ---------------------------------------------------------------------------
// Kernel 2: FA2 flash attention, tf32 mma + ldmatrix fragments.
// CTA = 128 queries. 256 threads / 8 warps, 16 q-rows per warp.
// K smem [key][d] (n-major for S); V smem [d][key] (n-major for PV).
// ---------------------------------------------------------------------------
#define K_LDS 68
#define V_LDS 68
#define KBYTES (64 * K_LDS * 4)
#define VBYTES (64 * V_LDS * 4)
#define ATTN_STAGE (KBYTES + VBYTES)
#define ATTN_SMEM (3 * ATTN_STAGE)

__global__ __launch_bounds__(256, 2) void flash_attn_tc2(const float* __restrict__ gate)
{
    extern __shared__ char smc[];
    const uint32_t smb = smem_u32(smc);

    const int bh = blockIdx.y;
    const int q0 = blockIdx.x * 128;
    const int tid  = threadIdx.x;
    const int wid  = tid >> 5;
    const int lane = tid & 31;
    const int qq   = lane & 3;
    const int lr   = lane >> 2;
    const int wrow = wid * 16;
    const int lds_row = (lane & 7) + ((lane & 16) >> 1);
    const int lds_col = (lane & 8) * 2;

    const float* Qg = g_Q + ((size_t)bh * TT) * DD;
    const float* Kg = g_K + (size_t)bh * TT * DD;
    const float* Vt = g_V + (size_t)bh * DD * TT;   // [d][t]

    // Q A-fragments (pre-scaled by 1/sqrt(D))
    uint32_t qa[8][4];
    {
        const int r0 = q0 + wrow + lr;
        const float scale = 0.125f;
#pragma unroll
        for (int kc = 0; kc < 8; kc++) {
            const int col = kc * 8 + qq;
            qa[kc][0] = __float_as_uint(Qg[(size_t)r0 * DD + col] * scale);
            qa[kc][1] = __float_as_uint(Qg[(size_t)(r0 + 8) * DD + col] * scale);
            qa[kc][2] = __float_as_uint(Qg[(size_t)r0 * DD + col + 4] * scale);
            qa[kc][3] = __float_as_uint(Qg[(size_t)(r0 + 8) * DD + col + 4] * scale);
        }
    }

    auto issue = [&](int kb) {
        const uint32_t Ku = smb + (kb % 3) * ATTN_STAGE;
        const uint32_t Vu = Ku + KBYTES;
        const float* Ksrc = Kg + (size_t)(kb * 64) * DD;
        const float* Vsrc = Vt + kb * 64;
#pragma unroll
        for (int i = 0; i < 4; i++) {
            const int ch = tid + i * 256;
            const int r = ch >> 4, cc = ch & 15;
            cp16(Ku + r * (K_LDS * 4) + cc * 16, Ksrc + (size_t)r * DD + cc * 4);
        }
#pragma unroll
        for (int i = 0; i < 4; i++) {
            const int ch = tid + i * 256;
            const int r = ch >> 4, cc = ch & 15;       // r = d row
            cp16(Vu + r * (V_LDS * 4) + cc * 16, Vsrc + (size_t)r * TT + cc * 4);
        }
        cp_commit();
    };

    float oc[8][4];
#pragma unroll
    for (int j = 0; j < 8; j++)
#pragma unroll
        for (int k = 0; k < 4; k++) oc[j][k] = 0.f;
    float m0 = -1e30f, m1 = -1e30f, l0 = 0.f, l1 = 0.f;

    issue(0);
    issue(1);

    for (int kb = 0; kb < TT / 64; kb++) {
        if (kb == TT / 64 - 1) cp_wait0(); else cp_wait1();
        __syncthreads();
        if (kb + 2 < TT / 64) issue(kb + 2);

        const uint32_t Ku = smb + (kb % 3) * ATTN_STAGE;
        const uint32_t koff = Ku + lds_row * (K_LDS * 4) + lds_col;
        const uint32_t voff = Ku + KBYTES + lds_row * (V_LDS * 4) + lds_col;

        // ---- S = Q K^T (16 x 64 per warp) via ldmatrix B-frags ----
        float sc[8][4];
#pragma unroll
        for (int j = 0; j < 8; j++)
#pragma unroll
            for (int k = 0; k < 4; k++) sc[j][k] = 0.f;

#pragma unroll
        for (int kc = 0; kc < 8; kc++) {
#pragma unroll
            for (int jp = 0; jp < 4; jp++) {
                uint32_t b[4];
                ldsm4(koff + jp * 16 * (K_LDS * 4) + kc * 32, b[0], b[1], b[2], b[3]);
                mma_tf32(sc[jp * 2],     qa[kc], b,     sc[jp * 2]);
                mma_tf32(sc[jp * 2 + 1], qa[kc], b + 2, sc[jp * 2 + 1]);
            }
        }

        // ---- Online softmax ----
        float mx0 = -1e30f, mx1 = -1e30f;
#pragma unroll
        for (int j = 0; j < 8; j++) {
            mx0 = fmaxf(mx0, fmaxf(sc[j][0], sc[j][1]));
            mx1 = fmaxf(mx1, fmaxf(sc[j][2], sc[j][3]));
        }
        mx0 = fmaxf(mx0, __shfl_xor_sync(0xffffffffu, mx0, 1));
        mx0 = fmaxf(mx0, __shfl_xor_sync(0xffffffffu, mx0, 2));
        mx1 = fmaxf(mx1, __shfl_xor_sync(0xffffffffu, mx1, 1));
        mx1 = fmaxf(mx1, __shfl_xor_sync(0xffffffffu, mx1, 2));

        const float mn0 = fmaxf(m0, mx0);
        const float mn1 = fmaxf(m1, mx1);
        const float al0 = __expf(m0 - mn0);
        const float al1 = __expf(m1 - mn1);

        float s0 = 0.f, s1 = 0.f;
#pragma unroll
        for (int j = 0; j < 8; j++) {
            sc[j][0] = __expf(sc[j][0] - mn0);
            sc[j][1] = __expf(sc[j][1] - mn0);
            sc[j][2] = __expf(sc[j][2] - mn1);
            sc[j][3] = __expf(sc[j][3] - mn1);
            s0 += sc[j][0] + sc[j][1];
            s1 += sc[j][2] + sc[j][3];
        }
        s0 += __shfl_xor_sync(0xffffffffu, s0, 1);
        s0 += __shfl_xor_sync(0xffffffffu, s0, 2);
        s1 += __shfl_xor_sync(0xffffffffu, s1, 1);
        s1 += __shfl_xor_sync(0xffffffffu, s1, 2);

        l0 = l0 * al0 + s0;
        l1 = l1 * al1 + s1;
        m0 = mn0;
        m1 = mn1;

#pragma unroll
        for (int j = 0; j < 8; j++) {
            oc[j][0] *= al0;
            oc[j][1] *= al0;
            oc[j][2] *= al1;
            oc[j][3] *= al1;
        }

        // ---- O += P V (P relaid C->A frag via quad shuffles; V via ldmatrix) ----
        const int src_a = (lane & 28) | (qq >> 1);
        const int src_b = src_a + 2;
#pragma unroll
        for (int kc2 = 0; kc2 < 8; kc2++) {
            const float x0 = __shfl_sync(0xffffffffu, sc[kc2][0], src_a);
            const float x1 = __shfl_sync(0xffffffffu, sc[kc2][1], src_a);
            const float y0 = __shfl_sync(0xffffffffu, sc[kc2][2], src_a);
            const float y1 = __shfl_sync(0xffffffffu, sc[kc2][3], src_a);
            const float z0 = __shfl_sync(0xffffffffu, sc[kc2][0], src_b);
            const float z1 = __shfl_sync(0xffffffffu, sc[kc2][1], src_b);
            const float w0 = __shfl_sync(0xffffffffu, sc[kc2][2], src_b);
            const float w1 = __shfl_sync(0xffffffffu, sc[kc2][3], src_b);
            uint32_t pa[4];
            pa[0] = __float_as_uint((qq & 1) ? x1 : x0);
            pa[1] = __float_as_uint((qq & 1) ? y1 : y0);
            pa[2] = __float_as_uint((qq & 1) ? z1 : z0);
            pa[3] = __float_as_uint((qq & 1) ? w1 : w0);
#pragma unroll
            for (int jp = 0; jp < 4; jp++) {
                uint32_t b[4];
                ldsm4(voff + jp * 16 * (V_LDS * 4) + kc2 * 32, b[0], b[1], b[2], b[3]);
                mma_tf32(oc[jp * 2],     pa, b,     oc[jp * 2]);
                mma_tf32(oc[jp * 2 + 1], pa, b + 2, oc[jp * 2 + 1]);
            }
        }
    }

    // ---- Epilogue: normalize, apply gate, write g_attn ----
    const int b  = bh >> 4;
    const int h  = bh & 15;
    const float g = gate[h];
    const float inv0 = g / l0;
    const float inv1 = g / l1;
    const int r0 = q0 + wrow + lr;
    float* row0 = g_attn + ((size_t)(b * TT + r0)) * EE + h * DD;
    float* row1 = g_attn + ((size_t)(b * TT + r0 + 8)) * EE + h * DD;
#pragma unroll
    for (int j = 0; j < 8; j++) {
        const int col = j * 8 + 2 * qq;
        float2 v0 = make_float2(oc[j][0] * inv0, oc[j][1] * inv0);
        float2 v1 = make_float2(oc[j][2] * inv1, oc[j][3] * inv1);
        *reinterpret_cast<float2*>(row0 + col) = v0;
        *reinterpret_cast<float2*>(row1 + col) = v1;
    }
}

// ---------------------------------------------------------------------------
extern "C" void kernel_launch(void* const* d_in, const int* in_sizes, int n_in,
                              void* d_out, int out_size)
{
    const float* X    = (const float*)d_in[0];
    const float* Wq   = (const float*)d_in[1];
    const float* bq   = (const float*)d_in[2];
    const float* Wk   = (const float*)d_in[3];
    const float* bk   = (const float*)d_in[4];
    const float* Wv   = (const float*)d_in[5];
    const float* bv   = (const float*)d_in[6];
    const float* Wo   = (const float*)d_in[7];
    const float* bo   = (const float*)d_in[8];
    const float* gate = (const float*)d_in[9];
    float* out = (float*)d_out;

    float* Wt_base;
    float* Wot_base;
    cudaGetSymbolAddress((void**)&Wt_base,  g_Wt);
    cudaGetSymbolAddress((void**)&Wot_base, g_Wot);

    cudaFuncSetAttribute(qkv_gemm_tc,    cudaFuncAttributeMaxDynamicSharedMemorySize, GEMM_SMEM);
    cudaFuncSetAttribute(out_gemm_tc,    cudaFuncAttributeMaxDynamicSharedMemorySize, GEMM_SMEM);
    cudaFuncSetAttribute(flash_attn_tc2, cudaFuncAttributeMaxDynamicSharedMemorySize, ATTN_SMEM);

    // 0) Transpose weights: Wq/Wk/Wv [H][E][D] -> Wt [mat][h*64+d][e];
    //    Wo [H*D][E] -> Wot [e][h*64+d].
    transpose2d<<<dim3(DD / 32, EE / 32, HH), dim3(32, 8)>>>(Wq, Wt_base + 0 * EE * EE, EE, DD);
    transpose2d<<<dim3(DD / 32, EE / 32, HH), dim3(32, 8)>>>(Wk, Wt_base + 1 * EE * EE, EE, DD);
    transpose2d<<<dim3(DD / 32, EE / 32, HH), dim3(32, 8)>>>(Wv, Wt_base + 2 * EE * EE, EE, DD);
    transpose2d<<<dim3(EE / 32, EE / 32, 1),  dim3(32, 8)>>>(Wo, Wot_base, EE, EE);

    // 1) QKV projection
    qkv_gemm_tc<<<dim3(3072 / 128, MM / 128), 256, GEMM_SMEM>>>(X, bq, bk, bv);
    // 2) Flash attention
    flash_attn_tc2<<<dim3(TT / 128, BH), 256, ATTN_SMEM>>>(gate);
    // 3) Output projection
    out_gemm_tc<<<dim3(EE / 128, MM / 128), 256, GEMM_SMEM>>>(bo, gate, out);
}

// round 7
// speedup vs baseline: 6.7723x; 1.8922x over previous
#include <cuda_runtime.h>
#include <cuda_fp16.h>
#include <cstdint>
#include <math.h>

// ---------------------------------------------------------------------------
// Problem constants
// ---------------------------------------------------------------------------
#define BB 2
#define TT 2048
#define EE 1024
#define HH 16
#define DD 64
#define MM (BB * TT)
#define BH (BB * HH)

// 0.125 (1/sqrt(64)) * log2(e): folded into Q so softmax uses ex2
#define SCALE_Q 0.18033688011112042f

// Scratch (device globals; allocation-free)
__device__ __half g_Xh[MM * EE];            // hidden fp16 [m][e]
__device__ __half g_Wth[3 * EE * EE];       // [mat][n=h*64+d][e] fp16
__device__ __half g_Woth[EE * EE];          // [n=e][k=h*64+d] fp16
__device__ __half g_Qh[BH * TT * DD];       // [bh][t][d] (pre-scaled by SCALE_Q)
__device__ __half g_Kh[BH * TT * DD];       // [bh][t][d]
__device__ __half g_Vh[BH * TT * DD];       // [bh][t][d]
__device__ __half g_attnh[MM * EE];         // gated attn out fp16 [m][h*64+d]

// ---------------------------------------------------------------------------
// Helpers
// ---------------------------------------------------------------------------
__device__ __forceinline__ uint32_t smem_u32(const void* p) {
    return (uint32_t)__cvta_generic_to_shared(p);
}
__device__ __forceinline__ void cp16(uint32_t dst, const void* src) {
    asm volatile("cp.async.cg.shared.global [%0], [%1], 16;\n" :: "r"(dst), "l"(src));
}
__device__ __forceinline__ void cp_commit() {
    asm volatile("cp.async.commit_group;\n" ::: "memory");
}
__device__ __forceinline__ void cp_wait1() {
    asm volatile("cp.async.wait_group 1;\n" ::: "memory");
}
__device__ __forceinline__ void cp_wait0() {
    asm volatile("cp.async.wait_group 0;\n" ::: "memory");
}
__device__ __forceinline__ void ldsm4(uint32_t addr, uint32_t& r0, uint32_t& r1,
                                      uint32_t& r2, uint32_t& r3) {
    asm volatile("ldmatrix.sync.aligned.m8n8.x4.shared.b16 {%0,%1,%2,%3}, [%4];"
                 : "=r"(r0), "=r"(r1), "=r"(r2), "=r"(r3) : "r"(addr));
}
__device__ __forceinline__ void ldsm4t(uint32_t addr, uint32_t& r0, uint32_t& r1,
                                       uint32_t& r2, uint32_t& r3) {
    asm volatile("ldmatrix.sync.aligned.m8n8.x4.trans.shared.b16 {%0,%1,%2,%3}, [%4];"
                 : "=r"(r0), "=r"(r1), "=r"(r2), "=r"(r3) : "r"(addr));
}
// m16n8k16 fp16 mma, fp32 accumulate
__device__ __forceinline__ void mma_f16(float* d, const uint32_t* a,
                                        uint32_t b0, uint32_t b1, const float* c) {
    asm volatile(
        "mma.sync.aligned.m16n8k16.row.col.f32.f16.f16.f32 "
        "{%0,%1,%2,%3}, {%4,%5,%6,%7}, {%8,%9}, {%10,%11,%12,%13};\n"
        : "=f"(d[0]), "=f"(d[1]), "=f"(d[2]), "=f"(d[3])
        : "r"(a[0]), "r"(a[1]), "r"(a[2]), "r"(a[3]),
          "r"(b0), "r"(b1),
          "f"(c[0]), "f"(c[1]), "f"(c[2]), "f"(c[3]));
}
__device__ __forceinline__ uint32_t packh2(float lo, float hi) {
    __half2 h = __floats2half2_rn(lo, hi);
    return *reinterpret_cast<uint32_t*>(&h);
}
__device__ __forceinline__ float ex2f(float x) {
    float r;
    asm("ex2.approx.f32 %0, %1;" : "=f"(r) : "f"(x));
    return r;
}

// ---------------------------------------------------------------------------
// Conversion kernels
// ---------------------------------------------------------------------------
__global__ void cvt_x(const float* __restrict__ src, __half* __restrict__ dst)
{
    const int f = blockIdx.x * 256 + threadIdx.x;   // float4 index
    float4 v = *reinterpret_cast<const float4*>(src + (size_t)f * 4);
    uint2 o;
    o.x = packh2(v.x, v.y);
    o.y = packh2(v.z, v.w);
    *reinterpret_cast<uint2*>(dst + (size_t)f * 4) = o;
}

// src fp32 [batch][R][C] -> dst fp16 [batch][C][R]
__global__ void cvt_transpose(const float* __restrict__ src, __half* __restrict__ dst,
                              int R, int C)
{
    __shared__ float tile[32][33];
    const int c0 = blockIdx.x * 32;
    const int r0 = blockIdx.y * 32;
    const size_t boff = (size_t)blockIdx.z * R * C;
#pragma unroll
    for (int i = 0; i < 4; i++) {
        const int r = r0 + threadIdx.y + i * 8;
        tile[threadIdx.y + i * 8][threadIdx.x] = src[boff + (size_t)r * C + c0 + threadIdx.x];
    }
    __syncthreads();
#pragma unroll
    for (int i = 0; i < 4; i++) {
        const int c = c0 + threadIdx.y + i * 8;
        dst[boff + (size_t)c * R + r0 + threadIdx.x] =
            __float2half_rn(tile[threadIdx.x][threadIdx.y + i * 8]);
    }
}

// ---------------------------------------------------------------------------
// GEMM smem: 3 stages of (A 128x40 halves, B 128x40 halves) = 20480 B/stage.
// Epilogue overlays: qkv uses fp16 Cs [128][136] (34816 B); out uses fp32
// Cs [128][132] (67584 B). Allocate 69632 B -> 2 CTAs/SM.
// ---------------------------------------------------------------------------
#define AH_LD 40          // halves
#define STAGE_BYTES 20480
#define GEMM_SMEM 69632
#define CH_LD 136         // halves (qkv epilogue)
#define CF_LD 132         // floats (out epilogue)

// ---------------------------------------------------------------------------
// Kernel 1: fused QKV projection, fp16 MMA. grid (24, 32).
// ---------------------------------------------------------------------------
__global__ __launch_bounds__(256, 2) void qkv_gemm_h(
    const float* __restrict__ bq, const float* __restrict__ bk,
    const float* __restrict__ bv)
{
    extern __shared__ char smc[];
    const uint32_t smb = smem_u32(smc);
    __shared__ float sbias[128];

    const int n0   = blockIdx.x * 128;
    const int m0   = blockIdx.y * 128;
    const int mat  = n0 >> 10;
    const int nloc = n0 & 1023;

    const __half* Wt  = g_Wth + (size_t)mat * EE * EE;
    const float* bias = (mat == 0 ? bq : (mat == 1 ? bk : bv));
    __half* dst       = (mat == 0 ? g_Qh : (mat == 1 ? g_Kh : g_Vh));
    const float qscale = (mat == 0) ? SCALE_Q : 1.0f;

    const int tid  = threadIdx.x;
    const int wid  = tid >> 5;
    const int lane = tid & 31;
    const int gr   = lane >> 2;
    const int tg   = lane & 3;
    const int wrow = (wid & 3) * 32;
    const int wcol = (wid >> 2) * 64;
    const int lrow = lane & 15;
    const int lcol = (lane >> 4) * 16;   // byte offset

    if (tid < 128) sbias[tid] = bias[nloc + tid];

    auto issue = [&](int kt) {
        const int k0 = kt * 32;          // halves
        const uint32_t Au = smb + (kt % 3) * STAGE_BYTES;
        const uint32_t Bu = Au + 10240;
#pragma unroll
        for (int i = 0; i < 2; i++) {
            const int ch = tid + i * 256;       // 0..511
            const int r = ch >> 2, c = ch & 3;
            cp16(Au + r * (AH_LD * 2) + c * 16, g_Xh + (size_t)(m0 + r) * EE + k0 + c * 8);
        }
#pragma unroll
        for (int i = 0; i < 2; i++) {
            const int ch = tid + i * 256;
            const int r = ch >> 2, c = ch & 3;
            cp16(Bu + r * (AH_LD * 2) + c * 16, Wt + (size_t)(nloc + r) * EE + k0 + c * 8);
        }
        cp_commit();
    };

    float acc[2][8][4];
#pragma unroll
    for (int i = 0; i < 2; i++)
#pragma unroll
        for (int j = 0; j < 8; j++)
#pragma unroll
            for (int k = 0; k < 4; k++) acc[i][j][k] = 0.f;

    issue(0);
    issue(1);

    for (int kt = 0; kt < 32; kt++) {
        if (kt == 31) cp_wait0(); else cp_wait1();
        __syncthreads();
        if (kt + 2 < 32) issue(kt + 2);

        const uint32_t Au = smb + (kt % 3) * STAGE_BYTES;
        const uint32_t aoffA = Au + (wrow + lrow) * (AH_LD * 2) + lcol;
        const uint32_t aoffB = Au + 10240 + (wcol + lrow) * (AH_LD * 2) + lcol;

#pragma unroll
        for (int kc = 0; kc < 2; kc++) {
            uint32_t a0[4], a1[4];
            ldsm4(aoffA + kc * 32, a0[0], a0[1], a0[2], a0[3]);
            ldsm4(aoffA + 16 * (AH_LD * 2) + kc * 32, a1[0], a1[1], a1[2], a1[3]);
#pragma unroll
            for (int jj = 0; jj < 4; jj++) {
                uint32_t b[4];
                ldsm4(aoffB + jj * 16 * (AH_LD * 2) + kc * 32, b[0], b[1], b[2], b[3]);
                mma_f16(acc[0][jj * 2],     a0, b[0], b[2], acc[0][jj * 2]);
                mma_f16(acc[0][jj * 2 + 1], a0, b[1], b[3], acc[0][jj * 2 + 1]);
                mma_f16(acc[1][jj * 2],     a1, b[0], b[2], acc[1][jj * 2]);
                mma_f16(acc[1][jj * 2 + 1], a1, b[1], b[3], acc[1][jj * 2 + 1]);
            }
        }
    }

    __syncthreads();
    __half* Csh = reinterpret_cast<__half*>(smc);
#pragma unroll
    for (int i = 0; i < 2; i++)
#pragma unroll
        for (int n8 = 0; n8 < 8; n8++) {
            const int row = wrow + i * 16 + gr;
            const int col = wcol + n8 * 8 + 2 * tg;
            const float b0 = sbias[col], b1 = sbias[col + 1];
            *reinterpret_cast<uint32_t*>(Csh + row * CH_LD + col) =
                packh2((acc[i][n8][0] + b0) * qscale, (acc[i][n8][1] + b1) * qscale);
            *reinterpret_cast<uint32_t*>(Csh + (row + 8) * CH_LD + col) =
                packh2((acc[i][n8][2] + b0) * qscale, (acc[i][n8][3] + b1) * qscale);
        }
    __syncthreads();

    const int bb = m0 >> 11;
#pragma unroll
    for (int i = 0; i < 8; i++) {
        const int f = tid + i * 256;       // 0..2047, 8-half chunks
        const int r = f >> 4;
        const int c8 = (f & 15) * 8;
        const int t = (m0 & (TT - 1)) + r;
        const int n = nloc + c8;
        const int h = n >> 6, d = n & 63;
        uint4 v = *reinterpret_cast<const uint4*>(Csh + r * CH_LD + c8);
        *reinterpret_cast<uint4*>(dst + ((size_t)((bb * HH + h) * TT + t)) * DD + d) = v;
    }
}

// ---------------------------------------------------------------------------
// Kernel 3: output projection, fp16 MMA. grid (8, 32). fp32 out + gated bias.
// ---------------------------------------------------------------------------
__global__ __launch_bounds__(256, 2) void out_gemm_h(
    const float* __restrict__ bo, const float* __restrict__ gate,
    float* __restrict__ out)
{
    extern __shared__ char smc[];
    const uint32_t smb = smem_u32(smc);
    __shared__ float gbias[128];

    const int n0 = blockIdx.x * 128;
    const int m0 = blockIdx.y * 128;

    const int tid  = threadIdx.x;
    const int wid  = tid >> 5;
    const int lane = tid & 31;
    const int gr   = lane >> 2;
    const int tg   = lane & 3;
    const int wrow = (wid & 3) * 32;
    const int wcol = (wid >> 2) * 64;
    const int lrow = lane & 15;
    const int lcol = (lane >> 4) * 16;

    if (tid < 128) {
        float s = 0.f;
#pragma unroll
        for (int hh = 0; hh < HH; hh++)
            s = fmaf(gate[hh], bo[(size_t)hh * EE + n0 + tid], s);
        gbias[tid] = s;
    }

    auto issue = [&](int kt) {
        const int k0 = kt * 32;
        const uint32_t Au = smb + (kt % 3) * STAGE_BYTES;
        const uint32_t Bu = Au + 10240;
#pragma unroll
        for (int i = 0; i < 2; i++) {
            const int ch = tid + i * 256;
            const int r = ch >> 2, c = ch & 3;
            cp16(Au + r * (AH_LD * 2) + c * 16, g_attnh + (size_t)(m0 + r) * EE + k0 + c * 8);
        }
#pragma unroll
        for (int i = 0; i < 2; i++) {
            const int ch = tid + i * 256;
            const int r = ch >> 2, c = ch & 3;
            cp16(Bu + r * (AH_LD * 2) + c * 16, g_Woth + (size_t)(n0 + r) * EE + k0 + c * 8);
        }
        cp_commit();
    };

    float acc[2][8][4];
#pragma unroll
    for (int i = 0; i < 2; i++)
#pragma unroll
        for (int j = 0; j < 8; j++)
#pragma unroll
            for (int k = 0; k < 4; k++) acc[i][j][k] = 0.f;

    issue(0);
    issue(1);

    for (int kt = 0; kt < 32; kt++) {
        if (kt == 31) cp_wait0(); else cp_wait1();
        __syncthreads();
        if (kt + 2 < 32) issue(kt + 2);

        const uint32_t Au = smb + (kt % 3) * STAGE_BYTES;
        const uint32_t aoffA = Au + (wrow + lrow) * (AH_LD * 2) + lcol;
        const uint32_t aoffB = Au + 10240 + (wcol + lrow) * (AH_LD * 2) + lcol;

#pragma unroll
        for (int kc = 0; kc < 2; kc++) {
            uint32_t a0[4], a1[4];
            ldsm4(aoffA + kc * 32, a0[0], a0[1], a0[2], a0[3]);
            ldsm4(aoffA + 16 * (AH_LD * 2) + kc * 32, a1[0], a1[1], a1[2], a1[3]);
#pragma unroll
            for (int jj = 0; jj < 4; jj++) {
                uint32_t b[4];
                ldsm4(aoffB + jj * 16 * (AH_LD * 2) + kc * 32, b[0], b[1], b[2], b[3]);
                mma_f16(acc[0][jj * 2],     a0, b[0], b[2], acc[0][jj * 2]);
                mma_f16(acc[0][jj * 2 + 1], a0, b[1], b[3], acc[0][jj * 2 + 1]);
                mma_f16(acc[1][jj * 2],     a1, b[0], b[2], acc[1][jj * 2]);
                mma_f16(acc[1][jj * 2 + 1], a1, b[1], b[3], acc[1][jj * 2 + 1]);
            }
        }
    }

    __syncthreads();
    float* Cs = reinterpret_cast<float*>(smc);
#pragma unroll
    for (int i = 0; i < 2; i++)
#pragma unroll
        for (int n8 = 0; n8 < 8; n8++) {
            const int row = wrow + i * 16 + gr;
            const int col = wcol + n8 * 8 + 2 * tg;
            *reinterpret_cast<float2*>(Cs + row * CF_LD + col) =
                make_float2(acc[i][n8][0], acc[i][n8][1]);
            *reinterpret_cast<float2*>(Cs + (row + 8) * CF_LD + col) =
                make_float2(acc[i][n8][2], acc[i][n8][3]);
        }
    __syncthreads();

#pragma unroll
    for (int i = 0; i < 16; i++) {
        const int f = tid + i * 256;
        const int r = f >> 5;
        const int c4 = (f & 31) * 4;
        float4 v = *reinterpret_cast<const float4*>(Cs + r * CF_LD + c4);
        v.x += gbias[c4 + 0];
        v.y += gbias[c4 + 1];
        v.z += gbias[c4 + 2];
        v.w += gbias[c4 + 3];
        *reinterpret_cast<float4*>(out + (size_t)(m0 + r) * EE + n0 + c4) = v;
    }
}

// ---------------------------------------------------------------------------
// Kernel 2: FA2 flash attention, fp16 MMA. CTA = 128 queries x bh.
// 256 threads / 8 warps, 16 q-rows each. fp16 C->A identity relay (no shfl),
// V used row-major via ldmatrix.trans. Softmax in fp32 (ex2; Q pre-scaled).
// Smem: Q 128x72h (18432 B) + 3 stages of (K 64x72h + V 64x72h = 18432 B).
// ---------------------------------------------------------------------------
#define KH_LD 72
#define KTILE_BYTES (64 * KH_LD * 2)   // 9216
#define ATTN_STAGE (2 * KTILE_BYTES)   // 18432
#define QTILE_BYTES (128 * KH_LD * 2)  // 18432
#define ATTN_SMEM (QTILE_BYTES + 3 * ATTN_STAGE)  // 73728

__global__ __launch_bounds__(256, 2) void flash_attn_h(const float* __restrict__ gate)
{
    extern __shared__ char smc[];
    const uint32_t smb = smem_u32(smc);
    const uint32_t Qu  = smb;
    const uint32_t St0 = smb + QTILE_BYTES;

    const int bh = blockIdx.y;
    const int q0 = blockIdx.x * 128;
    const int tid  = threadIdx.x;
    const int wid  = tid >> 5;
    const int lane = tid & 31;
    const int gr   = lane >> 2;
    const int tg   = lane & 3;
    const int wrow = wid * 16;
    const int lrow = lane & 15;
    const int lcol = (lane >> 4) * 16;

    const __half* Qg = g_Qh + ((size_t)bh * TT + q0) * DD;
    const __half* Kg = g_Kh + (size_t)bh * TT * DD;
    const __half* Vg = g_Vh + (size_t)bh * TT * DD;

    auto issueKV = [&](int kb) {
        const uint32_t Ku = St0 + (kb % 3) * ATTN_STAGE;
        const uint32_t Vu = Ku + KTILE_BYTES;
        const __half* Ksrc = Kg + (size_t)(kb * 64) * DD;
        const __half* Vsrc = Vg + (size_t)(kb * 64) * DD;
#pragma unroll
        for (int i = 0; i < 2; i++) {
            const int ch = tid + i * 256;     // 0..511
            const int r = ch >> 3, c = ch & 7;
            cp16(Ku + r * (KH_LD * 2) + c * 16, Ksrc + (size_t)r * DD + c * 8);
        }
#pragma unroll
        for (int i = 0; i < 2; i++) {
            const int ch = tid + i * 256;
            const int r = ch >> 3, c = ch & 7;
            cp16(Vu + r * (KH_LD * 2) + c * 16, Vsrc + (size_t)r * DD + c * 8);
        }
        cp_commit();
    };

    // Group 0 = Q tile + K/V tile 0
    {
#pragma unroll
        for (int i = 0; i < 4; i++) {
            const int ch = tid + i * 256;     // 0..1023
            const int r = ch >> 3, c = ch & 7;
            cp16(Qu + r * (KH_LD * 2) + c * 16, Qg + (size_t)r * DD + c * 8);
        }
        issueKV(0);   // commits group 0 (Q + KV0)
    }
    issueKV(1);       // group 1

    cp_wait1();       // Q + KV0 complete
    __syncthreads();

    // Q A-fragments: 4 k-chunks (d 0..63)
    uint32_t qa[4][4];
    {
        const uint32_t qoff = Qu + (wrow + lrow) * (KH_LD * 2) + lcol;
#pragma unroll
        for (int kc = 0; kc < 4; kc++)
            ldsm4(qoff + kc * 32, qa[kc][0], qa[kc][1], qa[kc][2], qa[kc][3]);
    }

    float oc[8][4];
#pragma unroll
    for (int j = 0; j < 8; j++)
#pragma unroll
        for (int k = 0; k < 4; k++) oc[j][k] = 0.f;
    float m0 = -1e30f, m1 = -1e30f, l0 = 0.f, l1 = 0.f;

    for (int kb = 0; kb < TT / 64; kb++) {
        if (kb == TT / 64 - 1) cp_wait0(); else cp_wait1();
        __syncthreads();
        if (kb + 2 < TT / 64) issueKV(kb + 2);

        const uint32_t Ku = St0 + (kb % 3) * ATTN_STAGE;
        const uint32_t koff = Ku + lrow * (KH_LD * 2) + lcol;
        const uint32_t voff = Ku + KTILE_BYTES + lrow * (KH_LD * 2) + lcol;

        // ---- S = Q K^T (16 x 64 per warp), log2-domain scores ----
        float sc[8][4];
#pragma unroll
        for (int j = 0; j < 8; j++)
#pragma unroll
            for (int k = 0; k < 4; k++) sc[j][k] = 0.f;

#pragma unroll
        for (int kc = 0; kc < 4; kc++) {
#pragma unroll
            for (int jp = 0; jp < 4; jp++) {
                uint32_t b[4];
                ldsm4(koff + jp * 16 * (KH_LD * 2) + kc * 32, b[0], b[1], b[2], b[3]);
                mma_f16(sc[jp * 2],     qa[kc], b[0], b[2], sc[jp * 2]);
                mma_f16(sc[jp * 2 + 1], qa[kc], b[1], b[3], sc[jp * 2 + 1]);
            }
        }

        // ---- Online softmax (base-2) ----
        float mx0 = -1e30f, mx1 = -1e30f;
#pragma unroll
        for (int j = 0; j < 8; j++) {
            mx0 = fmaxf(mx0, fmaxf(sc[j][0], sc[j][1]));
            mx1 = fmaxf(mx1, fmaxf(sc[j][2], sc[j][3]));
        }
        mx0 = fmaxf(mx0, __shfl_xor_sync(0xffffffffu, mx0, 1));
        mx0 = fmaxf(mx0, __shfl_xor_sync(0xffffffffu, mx0, 2));
        mx1 = fmaxf(mx1, __shfl_xor_sync(0xffffffffu, mx1, 1));
        mx1 = fmaxf(mx1, __shfl_xor_sync(0xffffffffu, mx1, 2));

        const float mn0 = fmaxf(m0, mx0);
        const float mn1 = fmaxf(m1, mx1);
        const float al0 = ex2f(m0 - mn0);
        const float al1 = ex2f(m1 - mn1);

        float s0 = 0.f, s1 = 0.f;
#pragma unroll
        for (int j = 0; j < 8; j++) {
            sc[j][0] = ex2f(sc[j][0] - mn0);
            sc[j][1] = ex2f(sc[j][1] - mn0);
            sc[j][2] = ex2f(sc[j][2] - mn1);
            sc[j][3] = ex2f(sc[j][3] - mn1);
            s0 += sc[j][0] + sc[j][1];
            s1 += sc[j][2] + sc[j][3];
        }
        s0 += __shfl_xor_sync(0xffffffffu, s0, 1);
        s0 += __shfl_xor_sync(0xffffffffu, s0, 2);
        s1 += __shfl_xor_sync(0xffffffffu, s1, 1);
        s1 += __shfl_xor_sync(0xffffffffu, s1, 2);

        l0 = l0 * al0 + s0;
        l1 = l1 * al1 + s1;
        m0 = mn0;
        m1 = mn1;

#pragma unroll
        for (int j = 0; j < 8; j++) {
            oc[j][0] *= al0;
            oc[j][1] *= al0;
            oc[j][2] *= al1;
            oc[j][3] *= al1;
        }

        // ---- O += P V : fp16 C-frag == A-frag layout, pure packing ----
#pragma unroll
        for (int kc = 0; kc < 4; kc++) {
            uint32_t pa[4];
            pa[0] = packh2(sc[2 * kc][0],     sc[2 * kc][1]);
            pa[1] = packh2(sc[2 * kc][2],     sc[2 * kc][3]);
            pa[2] = packh2(sc[2 * kc + 1][0], sc[2 * kc + 1][1]);
            pa[3] = packh2(sc[2 * kc + 1][2], sc[2 * kc + 1][3]);
#pragma unroll
            for (int jp = 0; jp < 4; jp++) {
                uint32_t b[4];
                ldsm4t(voff + kc * 16 * (KH_LD * 2) + jp * 32, b[0], b[1], b[2], b[3]);
                mma_f16(oc[jp * 2],     pa, b[0], b[1], oc[jp * 2]);
                mma_f16(oc[jp * 2 + 1], pa, b[2], b[3], oc[jp * 2 + 1]);
            }
        }
    }

    // ---- Epilogue: normalize, apply gate, write fp16 g_attnh ----
    const int b  = bh >> 4;
    const int h  = bh & 15;
    const float g = gate[h];
    const float inv0 = g / l0;
    const float inv1 = g / l1;
    const int r0 = q0 + wrow + gr;
    __half* row0 = g_attnh + ((size_t)(b * TT + r0)) * EE + h * DD;
    __half* row1 = g_attnh + ((size_t)(b * TT + r0 + 8)) * EE + h * DD;
#pragma unroll
    for (int j = 0; j < 8; j++) {
        const int col = j * 8 + 2 * tg;
        *reinterpret_cast<uint32_t*>(row0 + col) = packh2(oc[j][0] * inv0, oc[j][1] * inv0);
        *reinterpret_cast<uint32_t*>(row1 + col) = packh2(oc[j][2] * inv1, oc[j][3] * inv1);
    }
}

// ---------------------------------------------------------------------------
extern "C" void kernel_launch(void* const* d_in, const int* in_sizes, int n_in,
                              void* d_out, int out_size)
{
    const float* X    = (const float*)d_in[0];
    const float* Wq   = (const float*)d_in[1];
    const float* bq   = (const float*)d_in[2];
    const float* Wk   = (const float*)d_in[3];
    const float* bk   = (const float*)d_in[4];
    const float* Wv   = (const float*)d_in[5];
    const float* bv   = (const float*)d_in[6];
    const float* Wo   = (const float*)d_in[7];
    const float* bo   = (const float*)d_in[8];
    const float* gate = (const float*)d_in[9];
    float* out = (float*)d_out;

    __half* Xh;
    __half* Wth;
    __half* Woth;
    cudaGetSymbolAddress((void**)&Xh,   g_Xh);
    cudaGetSymbolAddress((void**)&Wth,  g_Wth);
    cudaGetSymbolAddress((void**)&Woth, g_Woth);

    cudaFuncSetAttribute(qkv_gemm_h,   cudaFuncAttributeMaxDynamicSharedMemorySize, GEMM_SMEM);
    cudaFuncSetAttribute(out_gemm_h,   cudaFuncAttributeMaxDynamicSharedMemorySize, GEMM_SMEM);
    cudaFuncSetAttribute(flash_attn_h, cudaFuncAttributeMaxDynamicSharedMemorySize, ATTN_SMEM);

    // 0) Conversions: X -> fp16; weights -> fp16 transposed
    cvt_x<<<(MM * EE) / 1024, 256>>>(X, Xh);
    cvt_transpose<<<dim3(DD / 32, EE / 32, HH), dim3(32, 8)>>>(Wq, Wth + 0 * EE * EE, EE, DD);
    cvt_transpose<<<dim3(DD / 32, EE / 32, HH), dim3(32, 8)>>>(Wk, Wth + 1 * EE * EE, EE, DD);
    cvt_transpose<<<dim3(DD / 32, EE / 32, HH), dim3(32, 8)>>>(Wv, Wth + 2 * EE * EE, EE, DD);
    cvt_transpose<<<dim3(EE / 32, EE / 32, 1),  dim3(32, 8)>>>(Wo, Woth, EE, EE);

    // 1) QKV projection (fp16 MMA)
    qkv_gemm_h<<<dim3(3072 / 128, MM / 128), 256, GEMM_SMEM>>>(bq, bk, bv);
    // 2) Flash attention (fp16 MMA)
    flash_attn_h<<<dim3(TT / 128, BH), 256, ATTN_SMEM>>>(gate);
    // 3) Output projection (fp16 MMA)
    out_gemm_h<<<dim3(EE / 128, MM / 128), 256, GEMM_SMEM>>>(bo, gate, out);
}

// round 8
// speedup vs baseline: 7.4259x; 1.0965x over previous
#include <cuda_runtime.h>
#include <cuda_fp16.h>
#include <cstdint>
#include <math.h>

// ---------------------------------------------------------------------------
// Problem constants
// ---------------------------------------------------------------------------
#define BB 2
#define TT 2048
#define EE 1024
#define HH 16
#define DD 64
#define MM (BB * TT)
#define BH (BB * HH)

// 0.125 (1/sqrt(64)) * log2(e): folded into Q so softmax uses exp2
#define SCALE_Q 0.18033688011112042f
#define ONES_H2 0x3C003C00u

// Scratch (device globals; allocation-free)
__device__ __half g_Xh[MM * EE];            // hidden fp16 [m][e]
__device__ __half g_Wth[3 * EE * EE];       // [mat][n=h*64+d][e] fp16
__device__ __half g_Woth[EE * EE];          // [n=e][k=h*64+d] fp16
__device__ __half g_Qh[BH * TT * DD];       // [bh][t][d] (pre-scaled by SCALE_Q)
__device__ __half g_Kh[BH * TT * DD];       // [bh][t][d]
__device__ __half g_Vh[BH * TT * DD];       // [bh][t][d]
__device__ __half g_attnh[MM * EE];         // gated attn out fp16 [m][h*64+d]

// ---------------------------------------------------------------------------
// Helpers
// ---------------------------------------------------------------------------
__device__ __forceinline__ uint32_t smem_u32(const void* p) {
    return (uint32_t)__cvta_generic_to_shared(p);
}
__device__ __forceinline__ void cp16(uint32_t dst, const void* src) {
    asm volatile("cp.async.cg.shared.global [%0], [%1], 16;\n" :: "r"(dst), "l"(src));
}
__device__ __forceinline__ void cp_commit() {
    asm volatile("cp.async.commit_group;\n" ::: "memory");
}
__device__ __forceinline__ void cp_wait1() {
    asm volatile("cp.async.wait_group 1;\n" ::: "memory");
}
__device__ __forceinline__ void cp_wait0() {
    asm volatile("cp.async.wait_group 0;\n" ::: "memory");
}
__device__ __forceinline__ void ldsm4(uint32_t addr, uint32_t& r0, uint32_t& r1,
                                      uint32_t& r2, uint32_t& r3) {
    asm volatile("ldmatrix.sync.aligned.m8n8.x4.shared.b16 {%0,%1,%2,%3}, [%4];"
                 : "=r"(r0), "=r"(r1), "=r"(r2), "=r"(r3) : "r"(addr));
}
__device__ __forceinline__ void ldsm4t(uint32_t addr, uint32_t& r0, uint32_t& r1,
                                       uint32_t& r2, uint32_t& r3) {
    asm volatile("ldmatrix.sync.aligned.m8n8.x4.trans.shared.b16 {%0,%1,%2,%3}, [%4];"
                 : "=r"(r0), "=r"(r1), "=r"(r2), "=r"(r3) : "r"(addr));
}
// m16n8k16 fp16 mma, fp32 accumulate
__device__ __forceinline__ void mma_f16(float* d, const uint32_t* a,
                                        uint32_t b0, uint32_t b1, const float* c) {
    asm volatile(
        "mma.sync.aligned.m16n8k16.row.col.f32.f16.f16.f32 "
        "{%0,%1,%2,%3}, {%4,%5,%6,%7}, {%8,%9}, {%10,%11,%12,%13};\n"
        : "=f"(d[0]), "=f"(d[1]), "=f"(d[2]), "=f"(d[3])
        : "r"(a[0]), "r"(a[1]), "r"(a[2]), "r"(a[3]),
          "r"(b0), "r"(b1),
          "f"(c[0]), "f"(c[1]), "f"(c[2]), "f"(c[3]));
}
__device__ __forceinline__ uint32_t packh2(float lo, float hi) {
    __half2 h = __floats2half2_rn(lo, hi);
    return *reinterpret_cast<uint32_t*>(&h);
}
// 2^x on a packed half2 built from two floats
__device__ __forceinline__ uint32_t exp2h2(float lo, float hi) {
    __half2 h = h2exp2(__floats2half2_rn(lo, hi));
    return *reinterpret_cast<uint32_t*>(&h);
}

// ---------------------------------------------------------------------------
// Conversion kernels
// ---------------------------------------------------------------------------
__global__ void cvt_x(const float* __restrict__ src, __half* __restrict__ dst)
{
    const int f = blockIdx.x * 256 + threadIdx.x;   // float4 index
    float4 v = *reinterpret_cast<const float4*>(src + (size_t)f * 4);
    uint2 o;
    o.x = packh2(v.x, v.y);
    o.y = packh2(v.z, v.w);
    *reinterpret_cast<uint2*>(dst + (size_t)f * 4) = o;
}

// src fp32 [batch][R][C] -> dst fp16 [batch][C][R]
__global__ void cvt_transpose(const float* __restrict__ src, __half* __restrict__ dst,
                              int R, int C)
{
    __shared__ float tile[32][33];
    const int c0 = blockIdx.x * 32;
    const int r0 = blockIdx.y * 32;
    const size_t boff = (size_t)blockIdx.z * R * C;
#pragma unroll
    for (int i = 0; i < 4; i++) {
        const int r = r0 + threadIdx.y + i * 8;
        tile[threadIdx.y + i * 8][threadIdx.x] = src[boff + (size_t)r * C + c0 + threadIdx.x];
    }
    __syncthreads();
#pragma unroll
    for (int i = 0; i < 4; i++) {
        const int c = c0 + threadIdx.y + i * 8;
        dst[boff + (size_t)c * R + r0 + threadIdx.x] =
            __float2half_rn(tile[threadIdx.x][threadIdx.y + i * 8]);
    }
}

// Fused QKV weight transpose: z in [0,48), mat = z>>4, h = z&15.
// src Wx[h] is [E][D] fp32 -> dst g_Wth[mat][h*64 + d][e] fp16.
__global__ void cvt_transpose_qkv(const float* __restrict__ Wq,
                                  const float* __restrict__ Wk,
                                  const float* __restrict__ Wv,
                                  __half* __restrict__ dst)
{
    __shared__ float tile[32][33];
    const int z   = blockIdx.z;
    const int mat = z >> 4;
    const int h   = z & 15;
    const float* src = (mat == 0 ? Wq : (mat == 1 ? Wk : Wv)) + (size_t)h * EE * DD;
    __half* d = dst + (size_t)mat * EE * EE + (size_t)h * DD * EE;

    const int c0 = blockIdx.x * 32;   // D
    const int r0 = blockIdx.y * 32;   // E
#pragma unroll
    for (int i = 0; i < 4; i++) {
        const int r = r0 + threadIdx.y + i * 8;
        tile[threadIdx.y + i * 8][threadIdx.x] = src[(size_t)r * DD + c0 + threadIdx.x];
    }
    __syncthreads();
#pragma unroll
    for (int i = 0; i < 4; i++) {
        const int c = c0 + threadIdx.y + i * 8;
        d[(size_t)c * EE + r0 + threadIdx.x] =
            __float2half_rn(tile[threadIdx.x][threadIdx.y + i * 8]);
    }
}

// ---------------------------------------------------------------------------
// GEMM smem: 3 stages of (A 128x72 halves, B 128x72 halves) = 36864 B/stage.
// BK = 64 halves -> 16 mainloop iterations. Total 110592 B, 2 CTAs/SM.
// Epilogue overlays stage memory (fp16 Cs 128x136 = 34816 B; fp32 Cs
// 128x132x4 = 67584 B).
// ---------------------------------------------------------------------------
#define AH_LD 72          // halves (144 B row)
#define STAGE_BYTES 36864
#define BOFF 18432
#define GEMM_SMEM (3 * STAGE_BYTES)
#define CH_LD 136         // halves (qkv epilogue)
#define CF_LD 132         // floats (out epilogue)

// ---------------------------------------------------------------------------
// Kernel 1: fused QKV projection, fp16 MMA. grid (24, 32).
// ---------------------------------------------------------------------------
__global__ __launch_bounds__(256, 2) void qkv_gemm_h(
    const float* __restrict__ bq, const float* __restrict__ bk,
    const float* __restrict__ bv)
{
    extern __shared__ char smc[];
    const uint32_t smb = smem_u32(smc);
    __shared__ float sbias[128];

    const int n0   = blockIdx.x * 128;
    const int m0   = blockIdx.y * 128;
    const int mat  = n0 >> 10;
    const int nloc = n0 & 1023;

    const __half* Wt  = g_Wth + (size_t)mat * EE * EE;
    const float* bias = (mat == 0 ? bq : (mat == 1 ? bk : bv));
    __half* dst       = (mat == 0 ? g_Qh : (mat == 1 ? g_Kh : g_Vh));
    const float qscale = (mat == 0) ? SCALE_Q : 1.0f;

    const int tid  = threadIdx.x;
    const int wid  = tid >> 5;
    const int lane = tid & 31;
    const int gr   = lane >> 2;
    const int tg   = lane & 3;
    const int wrow = (wid & 3) * 32;
    const int wcol = (wid >> 2) * 64;
    const int lrow = lane & 15;
    const int lcol = (lane >> 4) * 16;   // byte offset

    if (tid < 128) sbias[tid] = bias[nloc + tid];

    auto issue = [&](int kt) {
        const int k0 = kt * 64;          // halves
        const uint32_t Au = smb + (kt % 3) * STAGE_BYTES;
        const uint32_t Bu = Au + BOFF;
#pragma unroll
        for (int i = 0; i < 4; i++) {
            const int ch = tid + i * 256;       // 0..1023
            const int r = ch >> 3, c = ch & 7;
            cp16(Au + r * (AH_LD * 2) + c * 16, g_Xh + (size_t)(m0 + r) * EE + k0 + c * 8);
        }
#pragma unroll
        for (int i = 0; i < 4; i++) {
            const int ch = tid + i * 256;
            const int r = ch >> 3, c = ch & 7;
            cp16(Bu + r * (AH_LD * 2) + c * 16, Wt + (size_t)(nloc + r) * EE + k0 + c * 8);
        }
        cp_commit();
    };

    float acc[2][8][4];
#pragma unroll
    for (int i = 0; i < 2; i++)
#pragma unroll
        for (int j = 0; j < 8; j++)
#pragma unroll
            for (int k = 0; k < 4; k++) acc[i][j][k] = 0.f;

    issue(0);
    issue(1);

    for (int kt = 0; kt < 16; kt++) {
        if (kt == 15) cp_wait0(); else cp_wait1();
        __syncthreads();
        if (kt + 2 < 16) issue(kt + 2);

        const uint32_t Au = smb + (kt % 3) * STAGE_BYTES;
        const uint32_t aoffA = Au + (wrow + lrow) * (AH_LD * 2) + lcol;
        const uint32_t aoffB = Au + BOFF + (wcol + lrow) * (AH_LD * 2) + lcol;

#pragma unroll
        for (int kc = 0; kc < 4; kc++) {
            uint32_t a0[4], a1[4];
            ldsm4(aoffA + kc * 32, a0[0], a0[1], a0[2], a0[3]);
            ldsm4(aoffA + 16 * (AH_LD * 2) + kc * 32, a1[0], a1[1], a1[2], a1[3]);
#pragma unroll
            for (int jj = 0; jj < 4; jj++) {
                uint32_t b[4];
                ldsm4(aoffB + jj * 16 * (AH_LD * 2) + kc * 32, b[0], b[1], b[2], b[3]);
                mma_f16(acc[0][jj * 2],     a0, b[0], b[2], acc[0][jj * 2]);
                mma_f16(acc[0][jj * 2 + 1], a0, b[1], b[3], acc[0][jj * 2 + 1]);
                mma_f16(acc[1][jj * 2],     a1, b[0], b[2], acc[1][jj * 2]);
                mma_f16(acc[1][jj * 2 + 1], a1, b[1], b[3], acc[1][jj * 2 + 1]);
            }
        }
    }

    __syncthreads();
    __half* Csh = reinterpret_cast<__half*>(smc);
#pragma unroll
    for (int i = 0; i < 2; i++)
#pragma unroll
        for (int n8 = 0; n8 < 8; n8++) {
            const int row = wrow + i * 16 + gr;
            const int col = wcol + n8 * 8 + 2 * tg;
            const float b0 = sbias[col], b1 = sbias[col + 1];
            *reinterpret_cast<uint32_t*>(Csh + row * CH_LD + col) =
                packh2((acc[i][n8][0] + b0) * qscale, (acc[i][n8][1] + b1) * qscale);
            *reinterpret_cast<uint32_t*>(Csh + (row + 8) * CH_LD + col) =
                packh2((acc[i][n8][2] + b0) * qscale, (acc[i][n8][3] + b1) * qscale);
        }
    __syncthreads();

    const int bb = m0 >> 11;
#pragma unroll
    for (int i = 0; i < 8; i++) {
        const int f = tid + i * 256;       // 0..2047, 8-half chunks
        const int r = f >> 4;
        const int c8 = (f & 15) * 8;
        const int t = (m0 & (TT - 1)) + r;
        const int n = nloc + c8;
        const int h = n >> 6, d = n & 63;
        uint4 v = *reinterpret_cast<const uint4*>(Csh + r * CH_LD + c8);
        *reinterpret_cast<uint4*>(dst + ((size_t)((bb * HH + h) * TT + t)) * DD + d) = v;
    }
}

// ---------------------------------------------------------------------------
// Kernel 3: output projection, fp16 MMA. grid (8, 32). fp32 out + gated bias.
// ---------------------------------------------------------------------------
__global__ __launch_bounds__(256, 2) void out_gemm_h(
    const float* __restrict__ bo, const float* __restrict__ gate,
    float* __restrict__ out)
{
    extern __shared__ char smc[];
    const uint32_t smb = smem_u32(smc);
    __shared__ float gbias[128];

    const int n0 = blockIdx.x * 128;
    const int m0 = blockIdx.y * 128;

    const int tid  = threadIdx.x;
    const int wid  = tid >> 5;
    const int lane = tid & 31;
    const int gr   = lane >> 2;
    const int tg   = lane & 3;
    const int wrow = (wid & 3) * 32;
    const int wcol = (wid >> 2) * 64;
    const int lrow = lane & 15;
    const int lcol = (lane >> 4) * 16;

    if (tid < 128) {
        float s = 0.f;
#pragma unroll
        for (int hh = 0; hh < HH; hh++)
            s = fmaf(gate[hh], bo[(size_t)hh * EE + n0 + tid], s);
        gbias[tid] = s;
    }

    auto issue = [&](int kt) {
        const int k0 = kt * 64;
        const uint32_t Au = smb + (kt % 3) * STAGE_BYTES;
        const uint32_t Bu = Au + BOFF;
#pragma unroll
        for (int i = 0; i < 4; i++) {
            const int ch = tid + i * 256;
            const int r = ch >> 3, c = ch & 7;
            cp16(Au + r * (AH_LD * 2) + c * 16, g_attnh + (size_t)(m0 + r) * EE + k0 + c * 8);
        }
#pragma unroll
        for (int i = 0; i < 4; i++) {
            const int ch = tid + i * 256;
            const int r = ch >> 3, c = ch & 7;
            cp16(Bu + r * (AH_LD * 2) + c * 16, g_Woth + (size_t)(n0 + r) * EE + k0 + c * 8);
        }
        cp_commit();
    };

    float acc[2][8][4];
#pragma unroll
    for (int i = 0; i < 2; i++)
#pragma unroll
        for (int j = 0; j < 8; j++)
#pragma unroll
            for (int k = 0; k < 4; k++) acc[i][j][k] = 0.f;

    issue(0);
    issue(1);

    for (int kt = 0; kt < 16; kt++) {
        if (kt == 15) cp_wait0(); else cp_wait1();
        __syncthreads();
        if (kt + 2 < 16) issue(kt + 2);

        const uint32_t Au = smb + (kt % 3) * STAGE_BYTES;
        const uint32_t aoffA = Au + (wrow + lrow) * (AH_LD * 2) + lcol;
        const uint32_t aoffB = Au + BOFF + (wcol + lrow) * (AH_LD * 2) + lcol;

#pragma unroll
        for (int kc = 0; kc < 4; kc++) {
            uint32_t a0[4], a1[4];
            ldsm4(aoffA + kc * 32, a0[0], a0[1], a0[2], a0[3]);
            ldsm4(aoffA + 16 * (AH_LD * 2) + kc * 32, a1[0], a1[1], a1[2], a1[3]);
#pragma unroll
            for (int jj = 0; jj < 4; jj++) {
                uint32_t b[4];
                ldsm4(aoffB + jj * 16 * (AH_LD * 2) + kc * 32, b[0], b[1], b[2], b[3]);
                mma_f16(acc[0][jj * 2],     a0, b[0], b[2], acc[0][jj * 2]);
                mma_f16(acc[0][jj * 2 + 1], a0, b[1], b[3], acc[0][jj * 2 + 1]);
                mma_f16(acc[1][jj * 2],     a1, b[0], b[2], acc[1][jj * 2]);
                mma_f16(acc[1][jj * 2 + 1], a1, b[1], b[3], acc[1][jj * 2 + 1]);
            }
        }
    }

    __syncthreads();
    float* Cs = reinterpret_cast<float*>(smc);
#pragma unroll
    for (int i = 0; i < 2; i++)
#pragma unroll
        for (int n8 = 0; n8 < 8; n8++) {
            const int row = wrow + i * 16 + gr;
            const int col = wcol + n8 * 8 + 2 * tg;
            *reinterpret_cast<float2*>(Cs + row * CF_LD + col) =
                make_float2(acc[i][n8][0], acc[i][n8][1]);
            *reinterpret_cast<float2*>(Cs + (row + 8) * CF_LD + col) =
                make_float2(acc[i][n8][2], acc[i][n8][3]);
        }
    __syncthreads();

#pragma unroll
    for (int i = 0; i < 16; i++) {
        const int f = tid + i * 256;
        const int r = f >> 5;
        const int c4 = (f & 31) * 4;
        float4 v = *reinterpret_cast<const float4*>(Cs + r * CF_LD + c4);
        v.x += gbias[c4 + 0];
        v.y += gbias[c4 + 1];
        v.z += gbias[c4 + 2];
        v.w += gbias[c4 + 3];
        *reinterpret_cast<float4*>(out + (size_t)(m0 + r) * EE + n0 + c4) = v;
    }
}

// ---------------------------------------------------------------------------
// Kernel 2: FA2 flash attention, fp16 MMA. CTA = 128 queries x bh.
// 256 threads / 8 warps, 16 q-rows each. P computed directly in fp16 via
// h2exp2; row-sums (l) accumulated by a ones-column MMA (no shuffles).
// ---------------------------------------------------------------------------
#define KH_LD 72
#define KTILE_BYTES (64 * KH_LD * 2)   // 9216
#define ATTN_STAGE (2 * KTILE_BYTES)   // 18432
#define QTILE_BYTES (128 * KH_LD * 2)  // 18432
#define ATTN_SMEM (QTILE_BYTES + 3 * ATTN_STAGE)  // 73728

__global__ __launch_bounds__(256, 2) void flash_attn_h(const float* __restrict__ gate)
{
    extern __shared__ char smc[];
    const uint32_t smb = smem_u32(smc);
    const uint32_t Qu  = smb;
    const uint32_t St0 = smb + QTILE_BYTES;

    const int bh = blockIdx.y;
    const int q0 = blockIdx.x * 128;
    const int tid  = threadIdx.x;
    const int wid  = tid >> 5;
    const int lane = tid & 31;
    const int gr   = lane >> 2;
    const int tg   = lane & 3;
    const int wrow = wid * 16;
    const int lrow = lane & 15;
    const int lcol = (lane >> 4) * 16;

    const __half* Qg = g_Qh + ((size_t)bh * TT + q0) * DD;
    const __half* Kg = g_Kh + (size_t)bh * TT * DD;
    const __half* Vg = g_Vh + (size_t)bh * TT * DD;

    auto issueKV = [&](int kb) {
        const uint32_t Ku = St0 + (kb % 3) * ATTN_STAGE;
        const uint32_t Vu = Ku + KTILE_BYTES;
        const __half* Ksrc = Kg + (size_t)(kb * 64) * DD;
        const __half* Vsrc = Vg + (size_t)(kb * 64) * DD;
#pragma unroll
        for (int i = 0; i < 2; i++) {
            const int ch = tid + i * 256;     // 0..511
            const int r = ch >> 3, c = ch & 7;
            cp16(Ku + r * (KH_LD * 2) + c * 16, Ksrc + (size_t)r * DD + c * 8);
        }
#pragma unroll
        for (int i = 0; i < 2; i++) {
            const int ch = tid + i * 256;
            const int r = ch >> 3, c = ch & 7;
            cp16(Vu + r * (KH_LD * 2) + c * 16, Vsrc + (size_t)r * DD + c * 8);
        }
        cp_commit();
    };

    // Group 0 = Q tile + K/V tile 0
    {
#pragma unroll
        for (int i = 0; i < 4; i++) {
            const int ch = tid + i * 256;     // 0..1023
            const int r = ch >> 3, c = ch & 7;
            cp16(Qu + r * (KH_LD * 2) + c * 16, Qg + (size_t)r * DD + c * 8);
        }
        issueKV(0);   // commits group 0 (Q + KV0)
    }
    issueKV(1);       // group 1

    cp_wait1();       // Q + KV0 complete
    __syncthreads();

    // Q A-fragments: 4 k-chunks (d 0..63)
    uint32_t qa[4][4];
    {
        const uint32_t qoff = Qu + (wrow + lrow) * (KH_LD * 2) + lcol;
#pragma unroll
        for (int kc = 0; kc < 4; kc++)
            ldsm4(qoff + kc * 32, qa[kc][0], qa[kc][1], qa[kc][2], qa[kc][3]);
    }

    float oc[8][4];
    float lc[4];      // ones-column accumulator: lc[0]=row gr sum, lc[2]=row gr+8
#pragma unroll
    for (int j = 0; j < 8; j++)
#pragma unroll
        for (int k = 0; k < 4; k++) oc[j][k] = 0.f;
#pragma unroll
    for (int k = 0; k < 4; k++) lc[k] = 0.f;
    float m0 = -1e30f, m1 = -1e30f;

    for (int kb = 0; kb < TT / 64; kb++) {
        if (kb == TT / 64 - 1) cp_wait0(); else cp_wait1();
        __syncthreads();
        if (kb + 2 < TT / 64) issueKV(kb + 2);

        const uint32_t Ku = St0 + (kb % 3) * ATTN_STAGE;
        const uint32_t koff = Ku + lrow * (KH_LD * 2) + lcol;
        const uint32_t voff = Ku + KTILE_BYTES + lrow * (KH_LD * 2) + lcol;

        // ---- S = Q K^T (16 x 64 per warp), log2-domain scores ----
        float sc[8][4];
#pragma unroll
        for (int j = 0; j < 8; j++)
#pragma unroll
            for (int k = 0; k < 4; k++) sc[j][k] = 0.f;

#pragma unroll
        for (int kc = 0; kc < 4; kc++) {
#pragma unroll
            for (int jp = 0; jp < 4; jp++) {
                uint32_t b[4];
                ldsm4(koff + jp * 16 * (KH_LD * 2) + kc * 32, b[0], b[1], b[2], b[3]);
                mma_f16(sc[jp * 2],     qa[kc], b[0], b[2], sc[jp * 2]);
                mma_f16(sc[jp * 2 + 1], qa[kc], b[1], b[3], sc[jp * 2 + 1]);
            }
        }

        // ---- Online softmax (base-2): max via shuffles ----
        float mx0 = -1e30f, mx1 = -1e30f;
#pragma unroll
        for (int j = 0; j < 8; j++) {
            mx0 = fmaxf(mx0, fmaxf(sc[j][0], sc[j][1]));
            mx1 = fmaxf(mx1, fmaxf(sc[j][2], sc[j][3]));
        }
        mx0 = fmaxf(mx0, __shfl_xor_sync(0xffffffffu, mx0, 1));
        mx0 = fmaxf(mx0, __shfl_xor_sync(0xffffffffu, mx0, 2));
        mx1 = fmaxf(mx1, __shfl_xor_sync(0xffffffffu, mx1, 1));
        mx1 = fmaxf(mx1, __shfl_xor_sync(0xffffffffu, mx1, 2));

        const float mn0 = fmaxf(m0, mx0);
        const float mn1 = fmaxf(m1, mx1);
        float al0, al1;
        asm("ex2.approx.f32 %0, %1;" : "=f"(al0) : "f"(m0 - mn0));
        asm("ex2.approx.f32 %0, %1;" : "=f"(al1) : "f"(m1 - mn1));
        m0 = mn0;
        m1 = mn1;

        // Rescale O and l accumulators
#pragma unroll
        for (int j = 0; j < 8; j++) {
            oc[j][0] *= al0;
            oc[j][1] *= al0;
            oc[j][2] *= al1;
            oc[j][3] *= al1;
        }
        lc[0] *= al0; lc[1] *= al0; lc[2] *= al1; lc[3] *= al1;

        // ---- P = 2^(S - mn) directly in fp16 A-frag layout ----
        uint32_t pa[4][4];
#pragma unroll
        for (int kc = 0; kc < 4; kc++) {
            pa[kc][0] = exp2h2(sc[2 * kc][0] - mn0,     sc[2 * kc][1] - mn0);
            pa[kc][1] = exp2h2(sc[2 * kc][2] - mn1,     sc[2 * kc][3] - mn1);
            pa[kc][2] = exp2h2(sc[2 * kc + 1][0] - mn0, sc[2 * kc + 1][1] - mn0);
            pa[kc][3] = exp2h2(sc[2 * kc + 1][2] - mn1, sc[2 * kc + 1][3] - mn1);
        }

        // ---- O += P V ; l += P * ones (row-sum via MMA, no shuffles) ----
#pragma unroll
        for (int kc = 0; kc < 4; kc++) {
            mma_f16(lc, pa[kc], ONES_H2, ONES_H2, lc);
#pragma unroll
            for (int jp = 0; jp < 4; jp++) {
                uint32_t b[4];
                ldsm4t(voff + kc * 16 * (KH_LD * 2) + jp * 32, b[0], b[1], b[2], b[3]);
                mma_f16(oc[jp * 2],     pa[kc], b[0], b[1], oc[jp * 2]);
                mma_f16(oc[jp * 2 + 1], pa[kc], b[2], b[3], oc[jp * 2 + 1]);
            }
        }
    }

    // ---- Epilogue: normalize, apply gate, write fp16 g_attnh ----
    const int b  = bh >> 4;
    const int h  = bh & 15;
    const float g = gate[h];
    const float inv0 = g / lc[0];
    const float inv1 = g / lc[2];
    const int r0 = q0 + wrow + gr;
    __half* row0 = g_attnh + ((size_t)(b * TT + r0)) * EE + h * DD;
    __half* row1 = g_attnh + ((size_t)(b * TT + r0 + 8)) * EE + h * DD;
#pragma unroll
    for (int j = 0; j < 8; j++) {
        const int col = j * 8 + 2 * tg;
        *reinterpret_cast<uint32_t*>(row0 + col) = packh2(oc[j][0] * inv0, oc[j][1] * inv0);
        *reinterpret_cast<uint32_t*>(row1 + col) = packh2(oc[j][2] * inv1, oc[j][3] * inv1);
    }
}

// ---------------------------------------------------------------------------
extern "C" void kernel_launch(void* const* d_in, const int* in_sizes, int n_in,
                              void* d_out, int out_size)
{
    const float* X    = (const float*)d_in[0];
    const float* Wq   = (const float*)d_in[1];
    const float* bq   = (const float*)d_in[2];
    const float* Wk   = (const float*)d_in[3];
    const float* bk   = (const float*)d_in[4];
    const float* Wv   = (const float*)d_in[5];
    const float* bv   = (const float*)d_in[6];
    const float* Wo   = (const float*)d_in[7];
    const float* bo   = (const float*)d_in[8];
    const float* gate = (const float*)d_in[9];
    float* out = (float*)d_out;

    __half* Xh;
    __half* Wth;
    __half* Woth;
    cudaGetSymbolAddress((void**)&Xh,   g_Xh);
    cudaGetSymbolAddress((void**)&Wth,  g_Wth);
    cudaGetSymbolAddress((void**)&Woth, g_Woth);

    cudaFuncSetAttribute(qkv_gemm_h,   cudaFuncAttributeMaxDynamicSharedMemorySize, GEMM_SMEM);
    cudaFuncSetAttribute(out_gemm_h,   cudaFuncAttributeMaxDynamicSharedMemorySize, GEMM_SMEM);
    cudaFuncSetAttribute(flash_attn_h, cudaFuncAttributeMaxDynamicSharedMemorySize, ATTN_SMEM);

    // 0) Conversions: X -> fp16; weights -> fp16 transposed (fused QKV)
    cvt_x<<<(MM * EE) / 1024, 256>>>(X, Xh);
    cvt_transpose_qkv<<<dim3(DD / 32, EE / 32, 48), dim3(32, 8)>>>(Wq, Wk, Wv, Wth);
    cvt_transpose<<<dim3(EE / 32, EE / 32, 1), dim3(32, 8)>>>(Wo, Woth, EE, EE);

    // 1) QKV projection (fp16 MMA)
    qkv_gemm_h<<<dim3(3072 / 128, MM / 128), 256, GEMM_SMEM>>>(bq, bk, bv);
    // 2) Flash attention (fp16 MMA)
    flash_attn_h<<<dim3(TT / 128, BH), 256, ATTN_SMEM>>>(gate);
    // 3) Output projection (fp16 MMA)
    out_gemm_h<<<dim3(EE / 128, MM / 128), 256, GEMM_SMEM>>>(bo, gate, out);
}